// round 15
// baseline (speedup 1.0000x reference)
#include <cuda_runtime.h>
#include <cuda_fp16.h>
#include <cstdint>
#include <cstddef>

#define NN 15872
#define DD 129
#define HH 128
#define EE 253952
#define NHT 3968      // EE / 64 half-tiles
#define NODTILES 124  // NN / 128 exactly

static __device__ float g_interp[NN * DD];
static __device__ float g_pooled[NN * HH];
static __device__ float g_base[NN * HH];
static __device__ __half g_srcH[NN * HH];
static __device__ __half g_srcL[NN * HH];

// ---------------------------------------------------------------------------
static __device__ __forceinline__ uint32_t smem_u32(const void* p) {
    uint32_t a;
    asm("{ .reg .u64 t; cvta.to.shared.u64 t, %1; cvt.u32.u64 %0, t; }"
        : "=r"(a) : "l"(p));
    return a;
}

// XOR-swizzled byte offset inside an fp16 tile (256B rows, 16B units)
#define SWZ(row, k) ((((uint32_t)(row)) << 8) + \
                     (((((uint32_t)(k) >> 3) ^ ((uint32_t)(row) & 7u))) << 4) + \
                     ((((uint32_t)(k)) & 7u) << 1))

#define LDMATRIX_X4(r0, r1, r2, r3, addr) \
    asm volatile("ldmatrix.sync.aligned.m8n8.x4.shared.b16 {%0,%1,%2,%3}, [%4];" \
                 : "=r"(r0), "=r"(r1), "=r"(r2), "=r"(r3) : "r"(addr))

#define MMA16816(d, a, b0, b1) \
    asm volatile("mma.sync.aligned.m16n8k16.row.col.f32.f16.f16.f32 " \
                 "{%0,%1,%2,%3}, {%4,%5,%6,%7}, {%8,%9}, {%0,%1,%2,%3};" \
                 : "+f"((d)[0]), "+f"((d)[1]), "+f"((d)[2]), "+f"((d)[3]) \
                 : "r"((a)[0]), "r"((a)[1]), "r"((a)[2]), "r"((a)[3]), \
                   "r"(b0), "r"(b1))

#define CP_ASYNC16(dst, src) \
    asm volatile("cp.async.cg.shared.global [%0], [%1], 16;" \
                 :: "r"(dst), "l"(src))
#define CP_COMMIT() asm volatile("cp.async.commit_group;")
#define CP_WAIT0()  asm volatile("cp.async.wait_group 0;" ::: "memory")

// fp16 hi/lo split of a pair of floats (hi: rounded, lo: residual)
static __device__ __forceinline__ void split2h(float a, float b,
                                               uint32_t& hi, uint32_t& lo) {
    __half2 h = __floats2half2_rn(a, b);
    float ar = a - __half2float(__low2half(h));
    float br = b - __half2float(__high2half(h));
    __half2 l = __floats2half2_rn(ar, br);
    hi = *reinterpret_cast<uint32_t*>(&h);
    lo = *reinterpret_cast<uint32_t*>(&l);
}

// Fused 2-combination fp16 GEMM (Ah@Wh + Al@Wh), warp tile 16x64.
// Used by edge kernel (8 warps/group, M=64) and node kernels (16 warps, M=128).
static __device__ __forceinline__ void gemm16_fused2(
    uint32_t smb, uint32_t offAh, uint32_t offAl, uint32_t offWh,
    float (&acc)[8][4], int warp_m, int warp_n, int lid)
{
    const int mi  = lid >> 3;
    const int l7  = lid & 7;
    const int arow_d = l7 + ((mi & 1) << 3);
    const int akk_d  = (mi >> 1) << 3;
    const int brow_d = l7 + ((mi >> 1) << 3);
    const int bkk_d  = (mi & 1) << 3;

#pragma unroll
    for (int ks = 0; ks < 8; ks++) {
        const int k0 = ks * 16;
        uint32_t ah[4], al[4];
        {
            uint32_t sw = SWZ(warp_m * 16 + arow_d, k0 + akk_d);
            LDMATRIX_X4(ah[0], ah[1], ah[2], ah[3], smb + offAh + sw);
            LDMATRIX_X4(al[0], al[1], al[2], al[3], smb + offAl + sw);
        }
#pragma unroll
        for (int q = 0; q < 4; q++) {
            uint32_t sw = SWZ(warp_n * 64 + q * 16 + brow_d, k0 + bkk_d);
            uint32_t b0, b1, b2, b3;
            LDMATRIX_X4(b0, b1, b2, b3, smb + offWh + sw);
            MMA16816(acc[2 * q + 0], ah, b0, b1);
            MMA16816(acc[2 * q + 1], ah, b2, b3);
            MMA16816(acc[2 * q + 0], al, b0, b1);
            MMA16816(acc[2 * q + 1], al, b2, b3);
        }
    }
}

#define ZERO_ACC1(acc) \
    { _Pragma("unroll") for (int j_ = 0; j_ < 8; j_++) \
      _Pragma("unroll") for (int c_ = 0; c_ < 4; c_++) acc[j_][c_] = 0.f; }

// ===========================================================================
// base0 (512 thr, 16 warps): g_base = b1 + src_main @ W1m ;
// preconvert src -> g_srcH/L, zero pooled.
// ===========================================================================
#define B0_WH   0u
#define B0_AH   32768u
#define B0_AL   65536u
#define B0_W257 98304u
#define B0_B1   98816u
#define B0_C1   99328u
#define SMEM_B0 99840u

__global__ void __launch_bounds__(512, 1)
base0_kernel(const float* __restrict__ src,
             const float* __restrict__ W1,
             const float* __restrict__ b1)
{
    extern __shared__ char sm8[];
    const uint32_t smb = smem_u32(sm8);
    const int tid = threadIdx.x;
    const int wid = tid >> 5, lid = tid & 31;
    const int warp_m = wid >> 1, warp_n = wid & 1;   // warp_m 0..7
    const int rb = blockIdx.x * 128;

    for (int idx = tid; idx < HH * HH; idx += 512) {
        int j = idx >> 7, t = idx & 127;
        float w = W1[(129 + j) * HH + t];
        *reinterpret_cast<__half*>(sm8 + B0_WH + SWZ(t, j)) = __float2half_rn(w);
    }
    if (tid < 128) {
        ((float*)(sm8 + B0_W257))[tid] = W1[257 * HH + tid];
        ((float*)(sm8 + B0_B1))[tid]   = b1[tid];
    }
    uint32_t* gsh = reinterpret_cast<uint32_t*>(g_srcH);
    uint32_t* gsl = reinterpret_cast<uint32_t*>(g_srcL);
    for (int r = wid; r < 128; r += 16) {
        const float* row = src + (size_t)(rb + r) * DD;
        int c0 = lid * 4;
        float x0 = __ldg(row + c0 + 0), x1 = __ldg(row + c0 + 1);
        float x2 = __ldg(row + c0 + 2), x3 = __ldg(row + c0 + 3);
        uint2 hv, lv;
        split2h(x0, x1, hv.x, lv.x);
        split2h(x2, x3, hv.y, lv.y);
        uint32_t a = SWZ(r, c0);
        *reinterpret_cast<uint2*>(sm8 + B0_AH + a) = hv;
        *reinterpret_cast<uint2*>(sm8 + B0_AL + a) = lv;
        size_t gi = ((size_t)(rb + r) * HH + c0) >> 1;
        *reinterpret_cast<uint2*>(&gsh[gi]) = hv;
        *reinterpret_cast<uint2*>(&gsl[gi]) = lv;
        if (lid == 0) ((float*)(sm8 + B0_C1))[r] = __ldg(row + 128);
    }
    {
        float4 z = make_float4(0.f, 0.f, 0.f, 0.f);
        float4* gp = reinterpret_cast<float4*>(g_pooled + (size_t)rb * HH);
        for (int i = tid; i < 128 * HH / 4; i += 512) gp[i] = z;
    }
    __syncthreads();

    float acc[8][4];
    ZERO_ACC1(acc)
    gemm16_fused2(smb, B0_AH, B0_AL, B0_WH, acc, warp_m, warp_n, lid);

    const float* w7 = (const float*)(sm8 + B0_W257);
    const float* bb = (const float*)(sm8 + B0_B1);
    const float* c1 = (const float*)(sm8 + B0_C1);
    {
        int row0 = warp_m * 16 + (lid >> 2);
        int row1 = row0 + 8;
        float cv0 = c1[row0], cv1 = c1[row1];
#pragma unroll
        for (int nt = 0; nt < 8; nt++) {
            int col = warp_n * 64 + nt * 8 + ((lid & 3) << 1);
            float2 W7 = *reinterpret_cast<const float2*>(w7 + col);
            float2 BB = *reinterpret_cast<const float2*>(bb + col);
            float2 o0, o1;
            o0.x = acc[nt][0] + BB.x + cv0 * W7.x;
            o0.y = acc[nt][1] + BB.y + cv0 * W7.y;
            o1.x = acc[nt][2] + BB.x + cv1 * W7.x;
            o1.y = acc[nt][3] + BB.y + cv1 * W7.y;
            *reinterpret_cast<float2*>(g_base + (size_t)(rb + row0) * HH + col) = o0;
            *reinterpret_cast<float2*>(g_base + (size_t)(rb + row1) * HH + col) = o1;
        }
    }
}

// ===========================================================================
// edge kernel (unchanged from R14 best): 2 groups of 8 warps, dedicated H
// buffer, 3 barriers/iter, prefetch after GEMM1's barrier.
// ===========================================================================
#define OFF_H     65536u
#define OFF_W1H   131072u
#define OFF_W2H   163840u
#define OFF_SELF  196608u
#define OFF_C128  197632u
#define OFF_IOU   198656u
#define OFF_W128  199680u
#define OFF_W258  200192u
#define OFF_B2    200704u
#define SMEM_EDGE 201216u

__global__ void __launch_bounds__(512, 1)
edge_tc_kernel(const float* __restrict__ src,
               const float* __restrict__ add_info,
               const int*   __restrict__ nbr_idx,
               const int*   __restrict__ self_idx,
               const float* __restrict__ W1,
               const float* __restrict__ W2,
               const float* __restrict__ b2)
{
    extern __shared__ char sm8[];
    const uint32_t smb = smem_u32(sm8);
    const int tid = threadIdx.x;
    const int g   = tid >> 8;
    const int gt  = tid & 255;
    const int wid = gt >> 5, lid = gt & 31;
    const int warp_m = wid >> 1;
    const int warp_n = wid & 1;

    const uint32_t offAH = (uint32_t)g * 32768u;
    const uint32_t offAL = offAH + 16384u;
    const uint32_t offHH = OFF_H + (uint32_t)g * 32768u;
    const uint32_t offHL = offHH + 16384u;

    const int grow = gt >> 2;
    const int half = (gt >> 1) & 1;
    const int part = gt & 1;
    const __half* gsrc = half ? g_srcL : g_srcH;
    const uint32_t dstbase = smb + (half ? offAL : offAH) +
                             ((uint32_t)grow << 8);
    const uint32_t grx = (uint32_t)(grow & 7);

    int*   selfp[2] = {(int*)(sm8 + OFF_SELF + (g * 2 + 0) * 256),
                       (int*)(sm8 + OFF_SELF + (g * 2 + 1) * 256)};
    float* c128p[2] = {(float*)(sm8 + OFF_C128 + (g * 2 + 0) * 256),
                       (float*)(sm8 + OFF_C128 + (g * 2 + 1) * 256)};
    float* ioup[2]  = {(float*)(sm8 + OFF_IOU + (g * 2 + 0) * 256),
                       (float*)(sm8 + OFF_IOU + (g * 2 + 1) * 256)};

    const int stride2 = gridDim.x * 2;
    int ht = blockIdx.x * 2 + g;

    {
        int nb = __ldg(&nbr_idx[ht * 64 + grow]);
        if ((gt & 3) == 0) {
            selfp[0][grow] = __ldg(&self_idx[ht * 64 + grow]);
            c128p[0][grow] = __ldg(&src[(size_t)nb * DD + 128]);
            ioup[0][grow]  = __ldg(&add_info[ht * 64 + grow]);
        }
        const __half* rowp = gsrc + ((size_t)nb << 7);
#pragma unroll
        for (int uu = 0; uu < 8; uu++) {
            uint32_t u = (uint32_t)(part * 8 + uu);
            CP_ASYNC16(dstbase + ((u ^ grx) << 4), rowp + u * 8);
        }
        CP_COMMIT();
    }

    for (int idx = tid; idx < HH * HH; idx += 512) {
        int h = idx & 127, k = idx >> 7;
        uint32_t a = SWZ(h, k);
        *reinterpret_cast<__half*>(sm8 + OFF_W1H + a) = __float2half_rn(W1[idx]);
        *reinterpret_cast<__half*>(sm8 + OFF_W2H + a) = __float2half_rn(W2[idx]);
    }
    if (tid < 128) {
        ((float*)(sm8 + OFF_W128))[tid] = W1[128 * HH + tid];
        ((float*)(sm8 + OFF_W258))[tid] = W1[258 * HH + tid];
        ((float*)(sm8 + OFF_B2))[tid]   = b2[tid];
    }
    CP_WAIT0();
    __syncthreads();

    const float* w128s = (const float*)(sm8 + OFF_W128);
    const float* w258s = (const float*)(sm8 + OFF_W258);
    const float* b2s   = (const float*)(sm8 + OFF_B2);

#define BARG() asm volatile("bar.sync %0, 256;" :: "r"(g + 1) : "memory")

    int buf = 0;
    for (; ht < NHT; ht += stride2) {
        const int nht = ht + stride2;

        const int*   selfs = selfp[buf];
        const float* c128s = c128p[buf];
        const float* ious  = ioup[buf];

        float acc[8][4];
        ZERO_ACC1(acc)
        gemm16_fused2(smb, offAH, offAL, OFF_W1H, acc, warp_m, warp_n, lid);
        BARG();   // A reads done -> A free

        if (nht < NHT) {
            int nb_next = __ldg(&nbr_idx[nht * 64 + grow]);
            if ((gt & 3) == 0) {
                selfp[buf ^ 1][grow] = __ldg(&self_idx[nht * 64 + grow]);
                c128p[buf ^ 1][grow] = __ldg(&src[(size_t)nb_next * DD + 128]);
                ioup[buf ^ 1][grow]  = __ldg(&add_info[nht * 64 + grow]);
            }
            const __half* rowp = gsrc + ((size_t)nb_next << 7);
#pragma unroll
            for (int uu = 0; uu < 8; uu++) {
                uint32_t u = (uint32_t)(part * 8 + uu);
                CP_ASYNC16(dstbase + ((u ^ grx) << 4), rowp + u * 8);
            }
            CP_COMMIT();
        }

        {
            int row0 = warp_m * 16 + (lid >> 2);
            int row1 = row0 + 8;
            int s0 = selfs[row0], s1 = selfs[row1];
            float cA0 = c128s[row0], cA1 = c128s[row1];
            float iv0 = ious[row0],  iv1 = ious[row1];
            const float* bp0 = g_base + (size_t)s0 * HH;
            const float* bp1 = g_base + (size_t)s1 * HH;
#pragma unroll
            for (int nt = 0; nt < 8; nt++) {
                int col = warp_n * 64 + nt * 8 + ((lid & 3) << 1);
                float2 B0 = *reinterpret_cast<const float2*>(bp0 + col);
                float2 B1 = *reinterpret_cast<const float2*>(bp1 + col);
                float2 WA = *reinterpret_cast<const float2*>(w128s + col);
                float2 WI = *reinterpret_cast<const float2*>(w258s + col);
                float h00 = fmaxf(acc[nt][0] + B0.x + cA0 * WA.x + iv0 * WI.x, 0.f);
                float h01 = fmaxf(acc[nt][1] + B0.y + cA0 * WA.y + iv0 * WI.y, 0.f);
                float h10 = fmaxf(acc[nt][2] + B1.x + cA1 * WA.x + iv1 * WI.x, 0.f);
                float h11 = fmaxf(acc[nt][3] + B1.y + cA1 * WA.y + iv1 * WI.y, 0.f);
                uint32_t hi, lo;
                split2h(h00, h01, hi, lo);
                uint32_t a0 = SWZ(row0, col);
                *reinterpret_cast<uint32_t*>(sm8 + offHH + a0) = hi;
                *reinterpret_cast<uint32_t*>(sm8 + offHL + a0) = lo;
                split2h(h10, h11, hi, lo);
                uint32_t a1 = SWZ(row1, col);
                *reinterpret_cast<uint32_t*>(sm8 + offHH + a1) = hi;
                *reinterpret_cast<uint32_t*>(sm8 + offHL + a1) = lo;
            }
        }
        BARG();   // H ready

        ZERO_ACC1(acc)
        gemm16_fused2(smb, offHH, offHL, OFF_W2H, acc, warp_m, warp_n, lid);

        {
            int row0 = warp_m * 16 + (lid >> 2);
            int s0 = selfs[row0], s1 = selfs[row0 + 8];
            int* gp = reinterpret_cast<int*>(g_pooled);
#pragma unroll
            for (int nt = 0; nt < 8; nt++) {
                int col = warp_n * 64 + nt * 8 + ((lid & 3) << 1);
#pragma unroll
                for (int c = 0; c < 2; c++) {
                    float bv = b2s[col + c];
                    float v0 = fmaxf(acc[nt][0 + c] + bv, 0.f);
                    float v1 = fmaxf(acc[nt][2 + c] + bv, 0.f);
                    if (s0 == s1) {
                        atomicMax(gp + (size_t)s0 * HH + col + c,
                                  __float_as_int(fmaxf(v0, v1)));
                    } else {
                        atomicMax(gp + (size_t)s0 * HH + col + c,
                                  __float_as_int(v0));
                        atomicMax(gp + (size_t)s1 * HH + col + c,
                                  __float_as_int(v1));
                    }
                }
            }
        }

        CP_WAIT0();
        BARG();
        buf ^= 1;
    }
#undef BARG
}

// ===========================================================================
// wobase (512 thr): interp1 = src + bo0 + pooled @ Wo0 (write g_interp,
// g_srcH/L), then g_base = b1_1 + interp1_main @ W1m_1 ; zero g_pooled.
// ===========================================================================
#define WB_WOH  0u
#define WB_W1H  32768u
#define WB_AH   65536u
#define WB_AL   98304u
#define WB_BO   131072u
#define WB_B1   131616u
#define WB_W257 132128u
#define WB_WOC  132640u
#define WB_C1   133152u
#define SMEM_WB 133664u

__global__ void __launch_bounds__(512, 1)
wobase_kernel(const float* __restrict__ src,
              const float* __restrict__ Wo,
              const float* __restrict__ bo,
              const float* __restrict__ W1b,
              const float* __restrict__ b1b)
{
    extern __shared__ char sm8[];
    const uint32_t smb = smem_u32(sm8);
    const int tid = threadIdx.x;
    const int wid = tid >> 5, lid = tid & 31;
    const int warp_m = wid >> 1, warp_n = wid & 1;   // warp_m 0..7
    const int rb = blockIdx.x * 128;

    for (int idx = tid; idx < HH * HH; idx += 512) {
        int j = idx >> 7, c = idx & 127;
        uint32_t a = SWZ(c, j);
        *reinterpret_cast<__half*>(sm8 + WB_WOH + a) =
            __float2half_rn(Wo[j * DD + c]);
        *reinterpret_cast<__half*>(sm8 + WB_W1H + a) =
            __float2half_rn(W1b[(129 + j) * HH + c]);
    }
    if (tid < 128) {
        ((float*)(sm8 + WB_WOC))[tid]  = Wo[tid * DD + 128];
        ((float*)(sm8 + WB_W257))[tid] = W1b[257 * HH + tid];
        ((float*)(sm8 + WB_B1))[tid]   = b1b[tid];
    }
    for (int i = tid; i < DD; i += 512) ((float*)(sm8 + WB_BO))[i] = bo[i];
    __syncthreads();

    for (int r = wid; r < 128; r += 16) {
        const float* prow = g_pooled + (size_t)(rb + r) * HH;
        int c0 = lid * 4;
        float4 x = *reinterpret_cast<const float4*>(prow + c0);
        uint2 hv, lv;
        split2h(x.x, x.y, hv.x, lv.x);
        split2h(x.z, x.w, hv.y, lv.y);
        uint32_t a = SWZ(r, c0);
        *reinterpret_cast<uint2*>(sm8 + WB_AH + a) = hv;
        *reinterpret_cast<uint2*>(sm8 + WB_AL + a) = lv;
    }
    {
        const float* wocol = (const float*)(sm8 + WB_WOC);
        const float* bos   = (const float*)(sm8 + WB_BO);
        int r = tid >> 2, q = tid & 3;
        const float* prow = g_pooled + (size_t)(rb + r) * HH + q * 32;
        float s = 0.f;
#pragma unroll 4
        for (int j = 0; j < 32; j++) s = fmaf(prow[j], wocol[q * 32 + j], s);
        s += __shfl_xor_sync(0xffffffffu, s, 1);
        s += __shfl_xor_sync(0xffffffffu, s, 2);
        if (q == 0) {
            float v = s + __ldg(&src[(size_t)(rb + r) * DD + 128]) + bos[128];
            ((float*)(sm8 + WB_C1))[r] = v;
            g_interp[(size_t)(rb + r) * DD + 128] = v;
        }
    }
    __syncthreads();
    {
        float4 z = make_float4(0.f, 0.f, 0.f, 0.f);
        float4* gp = reinterpret_cast<float4*>(g_pooled + (size_t)rb * HH);
        for (int i = tid; i < 128 * HH / 4; i += 512) gp[i] = z;
    }

    float acc[8][4];
    ZERO_ACC1(acc)
    gemm16_fused2(smb, WB_AH, WB_AL, WB_WOH, acc, warp_m, warp_n, lid);
    __syncthreads();   // A reads done; overwrite A with interp1

    {
        const float* bos = (const float*)(sm8 + WB_BO);
        uint32_t* gsh = reinterpret_cast<uint32_t*>(g_srcH);
        uint32_t* gsl = reinterpret_cast<uint32_t*>(g_srcL);
        int row0 = warp_m * 16 + (lid >> 2);
        int row1 = row0 + 8;
#pragma unroll
        for (int nt = 0; nt < 8; nt++) {
            int col = warp_n * 64 + nt * 8 + ((lid & 3) << 1);
            float2 BB = *reinterpret_cast<const float2*>(bos + col);
            size_t o0 = (size_t)(rb + row0) * DD + col;
            size_t o1 = (size_t)(rb + row1) * DD + col;
            float i00 = acc[nt][0] + src[o0]     + BB.x;
            float i01 = acc[nt][1] + src[o0 + 1] + BB.y;
            float i10 = acc[nt][2] + src[o1]     + BB.x;
            float i11 = acc[nt][3] + src[o1 + 1] + BB.y;
            g_interp[o0] = i00; g_interp[o0 + 1] = i01;
            g_interp[o1] = i10; g_interp[o1 + 1] = i11;
            uint32_t hi, lo;
            split2h(i00, i01, hi, lo);
            uint32_t a0 = SWZ(row0, col);
            *reinterpret_cast<uint32_t*>(sm8 + WB_AH + a0) = hi;
            *reinterpret_cast<uint32_t*>(sm8 + WB_AL + a0) = lo;
            gsh[((size_t)(rb + row0) * HH + col) >> 1] = hi;
            gsl[((size_t)(rb + row0) * HH + col) >> 1] = lo;
            split2h(i10, i11, hi, lo);
            uint32_t a1 = SWZ(row1, col);
            *reinterpret_cast<uint32_t*>(sm8 + WB_AH + a1) = hi;
            *reinterpret_cast<uint32_t*>(sm8 + WB_AL + a1) = lo;
            gsh[((size_t)(rb + row1) * HH + col) >> 1] = hi;
            gsl[((size_t)(rb + row1) * HH + col) >> 1] = lo;
        }
    }
    __syncthreads();

    ZERO_ACC1(acc)
    gemm16_fused2(smb, WB_AH, WB_AL, WB_W1H, acc, warp_m, warp_n, lid);
    {
        const float* w7 = (const float*)(sm8 + WB_W257);
        const float* bb = (const float*)(sm8 + WB_B1);
        const float* c1 = (const float*)(sm8 + WB_C1);
        int row0 = warp_m * 16 + (lid >> 2);
        int row1 = row0 + 8;
        float cv0 = c1[row0], cv1 = c1[row1];
#pragma unroll
        for (int nt = 0; nt < 8; nt++) {
            int col = warp_n * 64 + nt * 8 + ((lid & 3) << 1);
            float2 W7 = *reinterpret_cast<const float2*>(w7 + col);
            float2 BB = *reinterpret_cast<const float2*>(bb + col);
            float2 o0, o1;
            o0.x = acc[nt][0] + BB.x + cv0 * W7.x;
            o0.y = acc[nt][1] + BB.y + cv0 * W7.y;
            o1.x = acc[nt][2] + BB.x + cv1 * W7.x;
            o1.y = acc[nt][3] + BB.y + cv1 * W7.y;
            *reinterpret_cast<float2*>(g_base + (size_t)(rb + row0) * HH + col) = o0;
            *reinterpret_cast<float2*>(g_base + (size_t)(rb + row1) * HH + col) = o1;
        }
    }
}

// ===========================================================================
// wofinal (512 thr): interp2 = g_interp + bo1 + pooled @ Wo1 (smem only),
// out = relu(interp2 @ fW1 + fb1) @ fW2 + fb2
// ===========================================================================
#define WF_WOH  0u
#define WF_AH   32768u
#define WF_AL   65536u
#define WF_FW   98304u
#define WF_FB1  131328u
#define WF_FW2  131584u
#define WF_BO   131840u
#define WF_C1   132384u
#define WF_WOC  132896u
#define SMEM_WF 133408u

__global__ void __launch_bounds__(512, 1)
wofinal_kernel(const float* __restrict__ Wo,
               const float* __restrict__ bo,
               const float* __restrict__ fW1, const float* __restrict__ fb1,
               const float* __restrict__ fW2, const float* __restrict__ fb2,
               float* __restrict__ out)
{
    extern __shared__ char sm8[];
    const uint32_t smb = smem_u32(sm8);
    const int tid = threadIdx.x;
    const int wid = tid >> 5, lid = tid & 31;
    const int warp_m = wid >> 1, warp_n = wid & 1;   // warp_m 0..7
    const int rb = blockIdx.x * 128;

    for (int idx = tid; idx < HH * HH; idx += 512) {
        int j = idx >> 7, c = idx & 127;
        *reinterpret_cast<__half*>(sm8 + WF_WOH + SWZ(c, j)) =
            __float2half_rn(Wo[j * DD + c]);
    }
    if (tid < 128) ((float*)(sm8 + WF_WOC))[tid] = Wo[tid * DD + 128];
    for (int i = tid; i < DD * 64; i += 512) ((float*)(sm8 + WF_FW))[i] = fW1[i];
    if (tid < 64) {
        ((float*)(sm8 + WF_FB1))[tid] = fb1[tid];
        ((float*)(sm8 + WF_FW2))[tid] = fW2[tid];
    }
    for (int i = tid; i < DD; i += 512) ((float*)(sm8 + WF_BO))[i] = bo[i];
    __syncthreads();

    for (int r = wid; r < 128; r += 16) {
        const float* prow = g_pooled + (size_t)(rb + r) * HH;
        int c0 = lid * 4;
        float4 x = *reinterpret_cast<const float4*>(prow + c0);
        uint2 hv, lv;
        split2h(x.x, x.y, hv.x, lv.x);
        split2h(x.z, x.w, hv.y, lv.y);
        uint32_t a = SWZ(r, c0);
        *reinterpret_cast<uint2*>(sm8 + WF_AH + a) = hv;
        *reinterpret_cast<uint2*>(sm8 + WF_AL + a) = lv;
    }
    {
        const float* wocol = (const float*)(sm8 + WF_WOC);
        const float* bos   = (const float*)(sm8 + WF_BO);
        int r = tid >> 2, q = tid & 3;
        const float* prow = g_pooled + (size_t)(rb + r) * HH + q * 32;
        float s = 0.f;
#pragma unroll 4
        for (int j = 0; j < 32; j++) s = fmaf(prow[j], wocol[q * 32 + j], s);
        s += __shfl_xor_sync(0xffffffffu, s, 1);
        s += __shfl_xor_sync(0xffffffffu, s, 2);
        if (q == 0)
            ((float*)(sm8 + WF_C1))[r] =
                s + __ldg(&g_interp[(size_t)(rb + r) * DD + 128]) + bos[128];
    }
    __syncthreads();

    float acc[8][4];
    ZERO_ACC1(acc)
    gemm16_fused2(smb, WF_AH, WF_AL, WF_WOH, acc, warp_m, warp_n, lid);
    __syncthreads();   // A reads done; overwrite with fp32 fT (col-major)

    {
        const float* bos = (const float*)(sm8 + WF_BO);
        float* fT = (float*)(sm8 + WF_AH);
        int row0 = warp_m * 16 + (lid >> 2);
        int row1 = row0 + 8;
#pragma unroll
        for (int nt = 0; nt < 8; nt++) {
            int col = warp_n * 64 + nt * 8 + ((lid & 3) << 1);
            float2 BB = *reinterpret_cast<const float2*>(bos + col);
            size_t o0 = (size_t)(rb + row0) * DD + col;
            size_t o1 = (size_t)(rb + row1) * DD + col;
            fT[col * 128 + row0]       = acc[nt][0] + g_interp[o0]     + BB.x;
            fT[(col + 1) * 128 + row0] = acc[nt][1] + g_interp[o0 + 1] + BB.y;
            fT[col * 128 + row1]       = acc[nt][2] + g_interp[o1]     + BB.x;
            fT[(col + 1) * 128 + row1] = acc[nt][3] + g_interp[o1 + 1] + BB.y;
        }
    }
    __syncthreads();

    // final MLP: 4 threads per row, 16 hidden units each
    {
        const float* fT  = (const float*)(sm8 + WF_AH);
        const float* fw1 = (const float*)(sm8 + WF_FW);
        const float* fb1s = (const float*)(sm8 + WF_FB1);
        const float* fw2s = (const float*)(sm8 + WF_FW2);
        const float* c1  = (const float*)(sm8 + WF_C1);
        int r = tid >> 2, q = tid & 3;
        float hacc[16];
#pragma unroll
        for (int u = 0; u < 16; u++) hacc[u] = fb1s[q * 16 + u];
        for (int k = 0; k < 128; k++) {
            float xv = fT[k * 128 + r];
            const float4* wrow = reinterpret_cast<const float4*>(fw1 + k * 64 + q * 16);
#pragma unroll
            for (int u4 = 0; u4 < 4; u4++) {
                float4 w = wrow[u4];
                hacc[u4 * 4 + 0] = fmaf(xv, w.x, hacc[u4 * 4 + 0]);
                hacc[u4 * 4 + 1] = fmaf(xv, w.y, hacc[u4 * 4 + 1]);
                hacc[u4 * 4 + 2] = fmaf(xv, w.z, hacc[u4 * 4 + 2]);
                hacc[u4 * 4 + 3] = fmaf(xv, w.w, hacc[u4 * 4 + 3]);
            }
        }
        {
            float xv = c1[r];
            const float4* wrow = reinterpret_cast<const float4*>(fw1 + 128 * 64 + q * 16);
#pragma unroll
            for (int u4 = 0; u4 < 4; u4++) {
                float4 w = wrow[u4];
                hacc[u4 * 4 + 0] = fmaf(xv, w.x, hacc[u4 * 4 + 0]);
                hacc[u4 * 4 + 1] = fmaf(xv, w.y, hacc[u4 * 4 + 1]);
                hacc[u4 * 4 + 2] = fmaf(xv, w.z, hacc[u4 * 4 + 2]);
                hacc[u4 * 4 + 3] = fmaf(xv, w.w, hacc[u4 * 4 + 3]);
            }
        }
        float v = 0.f;
#pragma unroll
        for (int u = 0; u < 16; u++)
            v = fmaf(fmaxf(hacc[u], 0.f), fw2s[q * 16 + u], v);
        v += __shfl_xor_sync(0xffffffffu, v, 1);
        v += __shfl_xor_sync(0xffffffffu, v, 2);
        if (q == 0) out[rb + r] = v + __ldg(fb2);
    }
}

// ---------------------------------------------------------------------------
extern "C" void kernel_launch(void* const* d_in, const int* in_sizes, int n_in,
                              void* d_out, int out_size)
{
    (void)in_sizes; (void)n_in; (void)out_size;

    const float* interp_in = (const float*)d_in[0];
    const float* add_info  = (const float*)d_in[1];
    const int*   nbr       = (const int*)d_in[3];
    const int*   self      = (const int*)d_in[4];
    const float* b0W1 = (const float*)d_in[5];
    const float* b0b1 = (const float*)d_in[6];
    const float* b0W2 = (const float*)d_in[7];
    const float* b0b2 = (const float*)d_in[8];
    const float* b0Wo = (const float*)d_in[9];
    const float* b0bo = (const float*)d_in[10];
    const float* b1W1 = (const float*)d_in[11];
    const float* b1b1 = (const float*)d_in[12];
    const float* b1W2 = (const float*)d_in[13];
    const float* b1b2 = (const float*)d_in[14];
    const float* b1Wo = (const float*)d_in[15];
    const float* b1bo = (const float*)d_in[16];
    const float* fW1  = (const float*)d_in[17];
    const float* fb1  = (const float*)d_in[18];
    const float* fW2  = (const float*)d_in[19];
    const float* fb2  = (const float*)d_in[20];
    float* out = (float*)d_out;

    float* ginterp = nullptr;
    cudaGetSymbolAddress((void**)&ginterp, g_interp);

    int nsm = 148;
    cudaDeviceGetAttribute(&nsm, cudaDevAttrMultiProcessorCount, 0);

    cudaFuncSetAttribute(base0_kernel,
        cudaFuncAttributeMaxDynamicSharedMemorySize, (int)SMEM_B0);
    cudaFuncSetAttribute(edge_tc_kernel,
        cudaFuncAttributeMaxDynamicSharedMemorySize, (int)SMEM_EDGE);
    cudaFuncSetAttribute(wobase_kernel,
        cudaFuncAttributeMaxDynamicSharedMemorySize, (int)SMEM_WB);
    cudaFuncSetAttribute(wofinal_kernel,
        cudaFuncAttributeMaxDynamicSharedMemorySize, (int)SMEM_WF);

    base0_kernel<<<NODTILES, 512, SMEM_B0>>>(interp_in, b0W1, b0b1);
    edge_tc_kernel<<<nsm, 512, SMEM_EDGE>>>(interp_in, add_info, nbr, self,
                                            b0W1, b0W2, b0b2);
    wobase_kernel<<<NODTILES, 512, SMEM_WB>>>(interp_in, b0Wo, b0bo,
                                              b1W1, b1b1);
    edge_tc_kernel<<<nsm, 512, SMEM_EDGE>>>(ginterp, add_info, nbr, self,
                                            b1W1, b1W2, b1b2);
    wofinal_kernel<<<NODTILES, 512, SMEM_WF>>>(b1Wo, b1bo, fW1, fb1,
                                               fW2, fb2, out);
}

// round 16
// speedup vs baseline: 1.0236x; 1.0236x over previous
#include <cuda_runtime.h>
#include <cuda_fp16.h>
#include <cstdint>
#include <cstddef>

#define NN 15872
#define DD 129
#define HH 128
#define EE 253952
#define NHT 3968      // EE / 64 half-tiles
#define NODTILES 124  // NN / 128 exactly

static __device__ float g_interp[NN * DD];
static __device__ float g_pooled[NN * HH];
static __device__ float g_base[NN * HH];
static __device__ __half g_srcH[NN * HH];
static __device__ __half g_srcL[NN * HH];
static __device__ int   g_cnt;

// ---------------------------------------------------------------------------
static __device__ __forceinline__ uint32_t smem_u32(const void* p) {
    uint32_t a;
    asm("{ .reg .u64 t; cvta.to.shared.u64 t, %1; cvt.u32.u64 %0, t; }"
        : "=r"(a) : "l"(p));
    return a;
}

// XOR-swizzled byte offset inside an fp16 tile (256B rows, 16B units)
#define SWZ(row, k) ((((uint32_t)(row)) << 8) + \
                     (((((uint32_t)(k) >> 3) ^ ((uint32_t)(row) & 7u))) << 4) + \
                     ((((uint32_t)(k)) & 7u) << 1))

#define LDMATRIX_X4(r0, r1, r2, r3, addr) \
    asm volatile("ldmatrix.sync.aligned.m8n8.x4.shared.b16 {%0,%1,%2,%3}, [%4];" \
                 : "=r"(r0), "=r"(r1), "=r"(r2), "=r"(r3) : "r"(addr))

#define MMA16816(d, a, b0, b1) \
    asm volatile("mma.sync.aligned.m16n8k16.row.col.f32.f16.f16.f32 " \
                 "{%0,%1,%2,%3}, {%4,%5,%6,%7}, {%8,%9}, {%0,%1,%2,%3};" \
                 : "+f"((d)[0]), "+f"((d)[1]), "+f"((d)[2]), "+f"((d)[3]) \
                 : "r"((a)[0]), "r"((a)[1]), "r"((a)[2]), "r"((a)[3]), \
                   "r"(b0), "r"(b1))

#define CP_ASYNC16(dst, src) \
    asm volatile("cp.async.cg.shared.global [%0], [%1], 16;" \
                 :: "r"(dst), "l"(src))
#define CP_COMMIT() asm volatile("cp.async.commit_group;")
#define CP_WAIT0()  asm volatile("cp.async.wait_group 0;" ::: "memory")

// fp16 hi/lo split of a pair of floats (hi: rounded, lo: residual)
static __device__ __forceinline__ void split2h(float a, float b,
                                               uint32_t& hi, uint32_t& lo) {
    __half2 h = __floats2half2_rn(a, b);
    float ar = a - __half2float(__low2half(h));
    float br = b - __half2float(__high2half(h));
    __half2 l = __floats2half2_rn(ar, br);
    hi = *reinterpret_cast<uint32_t*>(&h);
    lo = *reinterpret_cast<uint32_t*>(&l);
}

// ---------------------------------------------------------------------------
// One 128x128x128 fp16 GEMM pass, 8 warps, warp tile 32x64 (node kernels).
// ---------------------------------------------------------------------------
static __device__ __forceinline__ void gemm128(uint32_t smb, uint32_t offA,
                                               uint32_t offW,
                                               float (&acc)[2][8][4],
                                               int warp_m, int warp_n, int lid)
{
    const int mi  = lid >> 3;
    const int l7  = lid & 7;
    const int arow_d = l7 + ((mi & 1) << 3);
    const int akk_d  = (mi >> 1) << 3;
    const int brow_d = l7 + ((mi >> 1) << 3);
    const int bkk_d  = (mi & 1) << 3;

#pragma unroll
    for (int ks = 0; ks < 8; ks++) {
        const int k0 = ks * 16;
        uint32_t a[2][4];
#pragma unroll
        for (int mt = 0; mt < 2; mt++) {
            uint32_t ad = smb + offA +
                SWZ(warp_m * 32 + mt * 16 + arow_d, k0 + akk_d);
            LDMATRIX_X4(a[mt][0], a[mt][1], a[mt][2], a[mt][3], ad);
        }
#pragma unroll
        for (int q = 0; q < 4; q++) {
            uint32_t bd = smb + offW +
                SWZ(warp_n * 64 + q * 16 + brow_d, k0 + bkk_d);
            uint32_t b0, b1, b2, b3;
            LDMATRIX_X4(b0, b1, b2, b3, bd);
#pragma unroll
            for (int mt = 0; mt < 2; mt++) {
                MMA16816(acc[mt][2 * q + 0], a[mt], b0, b1);
                MMA16816(acc[mt][2 * q + 1], a[mt], b2, b3);
            }
        }
    }
}

// Fused 64x128x128 fp16 GEMM (2 combinations: Ah@Wh + Al@Wh), 8 warps of a
// group, warp tile 16x64. Fragments loaded once per ks.
static __device__ __forceinline__ void gemm16_fused2(
    uint32_t smb, uint32_t offAh, uint32_t offAl, uint32_t offWh,
    float (&acc)[8][4], int warp_m, int warp_n, int lid)
{
    const int mi  = lid >> 3;
    const int l7  = lid & 7;
    const int arow_d = l7 + ((mi & 1) << 3);
    const int akk_d  = (mi >> 1) << 3;
    const int brow_d = l7 + ((mi >> 1) << 3);
    const int bkk_d  = (mi & 1) << 3;

#pragma unroll
    for (int ks = 0; ks < 8; ks++) {
        const int k0 = ks * 16;
        uint32_t ah[4], al[4];
        {
            uint32_t sw = SWZ(warp_m * 16 + arow_d, k0 + akk_d);
            LDMATRIX_X4(ah[0], ah[1], ah[2], ah[3], smb + offAh + sw);
            LDMATRIX_X4(al[0], al[1], al[2], al[3], smb + offAl + sw);
        }
#pragma unroll
        for (int q = 0; q < 4; q++) {
            uint32_t sw = SWZ(warp_n * 64 + q * 16 + brow_d, k0 + bkk_d);
            uint32_t b0, b1, b2, b3;
            LDMATRIX_X4(b0, b1, b2, b3, smb + offWh + sw);
            MMA16816(acc[2 * q + 0], ah, b0, b1);
            MMA16816(acc[2 * q + 1], ah, b2, b3);
            MMA16816(acc[2 * q + 0], al, b0, b1);
            MMA16816(acc[2 * q + 1], al, b2, b3);
        }
    }
}

#define ZERO_ACC2(acc) \
    { _Pragma("unroll") for (int i_ = 0; i_ < 2; i_++) \
      _Pragma("unroll") for (int j_ = 0; j_ < 8; j_++) \
      _Pragma("unroll") for (int c_ = 0; c_ < 4; c_++) acc[i_][j_][c_] = 0.f; }
#define ZERO_ACC1(acc) \
    { _Pragma("unroll") for (int j_ = 0; j_ < 8; j_++) \
      _Pragma("unroll") for (int c_ = 0; c_ < 4; c_++) acc[j_][c_] = 0.f; }

// ===========================================================================
// base0 (256 thr): g_base = b1 + src_main @ W1m ; preconvert src -> g_srcH/L,
// zero pooled; reset edge work counter.
// ===========================================================================
#define B0_WH   0u
#define B0_AH   32768u
#define B0_AL   65536u
#define B0_W257 98304u
#define B0_B1   98816u
#define B0_C1   99328u
#define SMEM_B0 99840u

__global__ void __launch_bounds__(256, 1)
base0_kernel(const float* __restrict__ src,
             const float* __restrict__ W1,
             const float* __restrict__ b1)
{
    extern __shared__ char sm8[];
    const uint32_t smb = smem_u32(sm8);
    const int tid = threadIdx.x;
    const int wid = tid >> 5, lid = tid & 31;
    const int warp_m = wid >> 1, warp_n = wid & 1;
    const int rb = blockIdx.x * 128;

    if (blockIdx.x == 0 && tid == 0) g_cnt = 0;   // reset edge scheduler

    for (int idx = tid; idx < HH * HH; idx += 256) {
        int j = idx >> 7, t = idx & 127;
        float w = W1[(129 + j) * HH + t];
        *reinterpret_cast<__half*>(sm8 + B0_WH + SWZ(t, j)) = __float2half_rn(w);
    }
    if (tid < 128) {
        ((float*)(sm8 + B0_W257))[tid] = W1[257 * HH + tid];
        ((float*)(sm8 + B0_B1))[tid]   = b1[tid];
    }
    uint32_t* gsh = reinterpret_cast<uint32_t*>(g_srcH);
    uint32_t* gsl = reinterpret_cast<uint32_t*>(g_srcL);
    for (int r = wid; r < 128; r += 8) {
        const float* row = src + (size_t)(rb + r) * DD;
        int c0 = lid * 4;
        float x0 = __ldg(row + c0 + 0), x1 = __ldg(row + c0 + 1);
        float x2 = __ldg(row + c0 + 2), x3 = __ldg(row + c0 + 3);
        uint2 hv, lv;
        split2h(x0, x1, hv.x, lv.x);
        split2h(x2, x3, hv.y, lv.y);
        uint32_t a = SWZ(r, c0);
        *reinterpret_cast<uint2*>(sm8 + B0_AH + a) = hv;
        *reinterpret_cast<uint2*>(sm8 + B0_AL + a) = lv;
        size_t gi = ((size_t)(rb + r) * HH + c0) >> 1;
        *reinterpret_cast<uint2*>(&gsh[gi]) = hv;
        *reinterpret_cast<uint2*>(&gsl[gi]) = lv;
        if (lid == 0) ((float*)(sm8 + B0_C1))[r] = __ldg(row + 128);
    }
    {
        float4 z = make_float4(0.f, 0.f, 0.f, 0.f);
        float4* gp = reinterpret_cast<float4*>(g_pooled + (size_t)rb * HH);
        for (int i = tid; i < 128 * HH / 4; i += 256) gp[i] = z;
    }
    __syncthreads();

    float acc[2][8][4];
    ZERO_ACC2(acc)
    {
        const uint32_t pa[2] = {B0_AH, B0_AL};
#pragma unroll 1
        for (int p = 0; p < 2; p++)
            gemm128(smb, pa[p], B0_WH, acc, warp_m, warp_n, lid);
    }

    const float* w7 = (const float*)(sm8 + B0_W257);
    const float* bb = (const float*)(sm8 + B0_B1);
    const float* c1 = (const float*)(sm8 + B0_C1);
#pragma unroll
    for (int mt = 0; mt < 2; mt++) {
        int row0 = warp_m * 32 + mt * 16 + (lid >> 2);
        int row1 = row0 + 8;
        float cv0 = c1[row0], cv1 = c1[row1];
#pragma unroll
        for (int nt = 0; nt < 8; nt++) {
            int col = warp_n * 64 + nt * 8 + ((lid & 3) << 1);
            float2 W7 = *reinterpret_cast<const float2*>(w7 + col);
            float2 BB = *reinterpret_cast<const float2*>(bb + col);
            float2 o0, o1;
            o0.x = acc[mt][nt][0] + BB.x + cv0 * W7.x;
            o0.y = acc[mt][nt][1] + BB.y + cv0 * W7.y;
            o1.x = acc[mt][nt][2] + BB.x + cv1 * W7.x;
            o1.y = acc[mt][nt][3] + BB.y + cv1 * W7.y;
            *reinterpret_cast<float2*>(g_base + (size_t)(rb + row0) * HH + col) = o0;
            *reinterpret_cast<float2*>(g_base + (size_t)(rb + row1) * HH + col) = o1;
        }
    }
}

// ===========================================================================
// edge kernel: 2 groups of 8 warps, dedicated H buffer, 3 barriers/iter,
// DYNAMIC work-stealing via g_cnt (pull issued at top of iter, visible at
// the post-GEMM1 barrier -> zero extra barriers).
// ===========================================================================
#define OFF_H     65536u
#define OFF_W1H   131072u
#define OFF_W2H   163840u
#define OFF_SELF  196608u
#define OFF_C128  197632u
#define OFF_IOU   198656u
#define OFF_W128  199680u
#define OFF_W258  200192u
#define OFF_B2    200704u
#define OFF_NXT   201216u   // 2 ints (next tile index per group)
#define SMEM_EDGE 201232u

__global__ void __launch_bounds__(512, 1)
edge_tc_kernel(const float* __restrict__ src,
               const float* __restrict__ add_info,
               const int*   __restrict__ nbr_idx,
               const int*   __restrict__ self_idx,
               const float* __restrict__ W1,
               const float* __restrict__ W2,
               const float* __restrict__ b2)
{
    extern __shared__ char sm8[];
    const uint32_t smb = smem_u32(sm8);
    const int tid = threadIdx.x;
    const int g   = tid >> 8;
    const int gt  = tid & 255;
    const int wid = gt >> 5, lid = gt & 31;
    const int warp_m = wid >> 1;
    const int warp_n = wid & 1;

    const uint32_t offAH = (uint32_t)g * 32768u;
    const uint32_t offAL = offAH + 16384u;
    const uint32_t offHH = OFF_H + (uint32_t)g * 32768u;
    const uint32_t offHL = offHH + 16384u;

    const int grow = gt >> 2;
    const int half = (gt >> 1) & 1;
    const int part = gt & 1;
    const __half* gsrc = half ? g_srcL : g_srcH;
    const uint32_t dstbase = smb + (half ? offAL : offAH) +
                             ((uint32_t)grow << 8);
    const uint32_t grx = (uint32_t)(grow & 7);

    int*   nxtS     = (int*)(sm8 + OFF_NXT);
    int*   selfp[2] = {(int*)(sm8 + OFF_SELF + (g * 2 + 0) * 256),
                       (int*)(sm8 + OFF_SELF + (g * 2 + 1) * 256)};
    float* c128p[2] = {(float*)(sm8 + OFF_C128 + (g * 2 + 0) * 256),
                       (float*)(sm8 + OFF_C128 + (g * 2 + 1) * 256)};
    float* ioup[2]  = {(float*)(sm8 + OFF_IOU + (g * 2 + 0) * 256),
                       (float*)(sm8 + OFF_IOU + (g * 2 + 1) * 256)};

    // grab first tile
    if (gt == 0) nxtS[g] = atomicAdd(&g_cnt, 1);

    // ---- stage weights (all 512 threads) ----
    for (int idx = tid; idx < HH * HH; idx += 512) {
        int h = idx & 127, k = idx >> 7;
        uint32_t a = SWZ(h, k);
        *reinterpret_cast<__half*>(sm8 + OFF_W1H + a) = __float2half_rn(W1[idx]);
        *reinterpret_cast<__half*>(sm8 + OFF_W2H + a) = __float2half_rn(W2[idx]);
    }
    if (tid < 128) {
        ((float*)(sm8 + OFF_W128))[tid] = W1[128 * HH + tid];
        ((float*)(sm8 + OFF_W258))[tid] = W1[258 * HH + tid];
        ((float*)(sm8 + OFF_B2))[tid]   = b2[tid];
    }
    __syncthreads();

    const float* w128s = (const float*)(sm8 + OFF_W128);
    const float* w258s = (const float*)(sm8 + OFF_W258);
    const float* b2s   = (const float*)(sm8 + OFF_B2);

#define BARG() asm volatile("bar.sync %0, 256;" :: "r"(g + 1) : "memory")

    // ---- prologue: prefetch first half-tile into buf 0 ----
    {
        int ht = nxtS[g];
        int nb = __ldg(&nbr_idx[ht * 64 + grow]);
        if ((gt & 3) == 0) {
            selfp[0][grow] = __ldg(&self_idx[ht * 64 + grow]);
            c128p[0][grow] = __ldg(&src[(size_t)nb * DD + 128]);
            ioup[0][grow]  = __ldg(&add_info[ht * 64 + grow]);
        }
        const __half* rowp = gsrc + ((size_t)nb << 7);
#pragma unroll
        for (int uu = 0; uu < 8; uu++) {
            uint32_t u = (uint32_t)(part * 8 + uu);
            CP_ASYNC16(dstbase + ((u ^ grx) << 4), rowp + u * 8);
        }
        CP_COMMIT();
        CP_WAIT0();
    }
    BARG();

    int buf = 0;
    while (true) {
        // pull next tile index (visible at the post-GEMM1 barrier)
        if (gt == 0) nxtS[g] = atomicAdd(&g_cnt, 1);

        const int*   selfs = selfp[buf];
        const float* c128s = c128p[buf];
        const float* ious  = ioup[buf];

        // ---- layer-1 fused GEMM (reads A) ----
        float acc[8][4];
        ZERO_ACC1(acc)
        gemm16_fused2(smb, offAH, offAL, OFF_W1H, acc, warp_m, warp_n, lid);
        BARG();   // A reads done -> A free; nxtS visible

        const int nht = nxtS[g];

        // ---- prefetch next tile into A (covers epi1 + GEMM2 + epi2) ----
        if (nht < NHT) {
            int nb_next = __ldg(&nbr_idx[nht * 64 + grow]);
            if ((gt & 3) == 0) {
                selfp[buf ^ 1][grow] = __ldg(&self_idx[nht * 64 + grow]);
                c128p[buf ^ 1][grow] = __ldg(&src[(size_t)nb_next * DD + 128]);
                ioup[buf ^ 1][grow]  = __ldg(&add_info[nht * 64 + grow]);
            }
            const __half* rowp = gsrc + ((size_t)nb_next << 7);
#pragma unroll
            for (int uu = 0; uu < 8; uu++) {
                uint32_t u = (uint32_t)(part * 8 + uu);
                CP_ASYNC16(dstbase + ((u ^ grx) << 4), rowp + u * 8);
            }
            CP_COMMIT();
        }

        // ---- epilogue 1: finish layer-1, relu, write H buffer ----
        {
            int row0 = warp_m * 16 + (lid >> 2);
            int row1 = row0 + 8;
            int s0 = selfs[row0], s1 = selfs[row1];
            float cA0 = c128s[row0], cA1 = c128s[row1];
            float iv0 = ious[row0],  iv1 = ious[row1];
            const float* bp0 = g_base + (size_t)s0 * HH;
            const float* bp1 = g_base + (size_t)s1 * HH;
#pragma unroll
            for (int nt = 0; nt < 8; nt++) {
                int col = warp_n * 64 + nt * 8 + ((lid & 3) << 1);
                float2 B0 = *reinterpret_cast<const float2*>(bp0 + col);
                float2 B1 = *reinterpret_cast<const float2*>(bp1 + col);
                float2 WA = *reinterpret_cast<const float2*>(w128s + col);
                float2 WI = *reinterpret_cast<const float2*>(w258s + col);
                float h00 = fmaxf(acc[nt][0] + B0.x + cA0 * WA.x + iv0 * WI.x, 0.f);
                float h01 = fmaxf(acc[nt][1] + B0.y + cA0 * WA.y + iv0 * WI.y, 0.f);
                float h10 = fmaxf(acc[nt][2] + B1.x + cA1 * WA.x + iv1 * WI.x, 0.f);
                float h11 = fmaxf(acc[nt][3] + B1.y + cA1 * WA.y + iv1 * WI.y, 0.f);
                uint32_t hi, lo;
                split2h(h00, h01, hi, lo);
                uint32_t a0 = SWZ(row0, col);
                *reinterpret_cast<uint32_t*>(sm8 + offHH + a0) = hi;
                *reinterpret_cast<uint32_t*>(sm8 + offHL + a0) = lo;
                split2h(h10, h11, hi, lo);
                uint32_t a1 = SWZ(row1, col);
                *reinterpret_cast<uint32_t*>(sm8 + offHH + a1) = hi;
                *reinterpret_cast<uint32_t*>(sm8 + offHL + a1) = lo;
            }
        }
        BARG();   // H ready

        // ---- layer-2 fused GEMM (reads H) ----
        ZERO_ACC1(acc)
        gemm16_fused2(smb, offHH, offHL, OFF_W2H, acc, warp_m, warp_n, lid);

        // ---- epilogue 2: bias + relu + merged segment atomicMax ----
        {
            int row0 = warp_m * 16 + (lid >> 2);
            int s0 = selfs[row0], s1 = selfs[row0 + 8];
            int* gp = reinterpret_cast<int*>(g_pooled);
#pragma unroll
            for (int nt = 0; nt < 8; nt++) {
                int col = warp_n * 64 + nt * 8 + ((lid & 3) << 1);
#pragma unroll
                for (int c = 0; c < 2; c++) {
                    float bv = b2s[col + c];
                    float v0 = fmaxf(acc[nt][0 + c] + bv, 0.f);
                    float v1 = fmaxf(acc[nt][2 + c] + bv, 0.f);
                    if (s0 == s1) {
                        atomicMax(gp + (size_t)s0 * HH + col + c,
                                  __float_as_int(fmaxf(v0, v1)));
                    } else {
                        atomicMax(gp + (size_t)s0 * HH + col + c,
                                  __float_as_int(v0));
                        atomicMax(gp + (size_t)s1 * HH + col + c,
                                  __float_as_int(v1));
                    }
                }
            }
        }

        CP_WAIT0();   // next-tile A transfer (issued before epi1)
        BARG();       // A + scalars visible; orders H reads vs next epi1
        buf ^= 1;
        if (nht >= NHT) break;
    }
#undef BARG
}

// ===========================================================================
// wobase (256 thr): interp1 = src + bo0 + pooled @ Wo0 (write g_interp,
// g_srcH/L), then g_base = b1_1 + interp1_main @ W1m_1 ; zero g_pooled;
// reset edge work counter.
// ===========================================================================
#define WB_WOH  0u
#define WB_W1H  32768u
#define WB_AH   65536u
#define WB_AL   98304u
#define WB_BO   131072u
#define WB_B1   131616u
#define WB_W257 132128u
#define WB_WOC  132640u
#define WB_C1   133152u
#define SMEM_WB 133664u

__global__ void __launch_bounds__(256, 1)
wobase_kernel(const float* __restrict__ src,
              const float* __restrict__ Wo,
              const float* __restrict__ bo,
              const float* __restrict__ W1b,
              const float* __restrict__ b1b)
{
    extern __shared__ char sm8[];
    const uint32_t smb = smem_u32(sm8);
    const int tid = threadIdx.x;
    const int wid = tid >> 5, lid = tid & 31;
    const int warp_m = wid >> 1, warp_n = wid & 1;
    const int rb = blockIdx.x * 128;

    if (blockIdx.x == 0 && tid == 0) g_cnt = 0;   // reset edge scheduler

    for (int idx = tid; idx < HH * HH; idx += 256) {
        int j = idx >> 7, c = idx & 127;
        uint32_t a = SWZ(c, j);
        *reinterpret_cast<__half*>(sm8 + WB_WOH + a) =
            __float2half_rn(Wo[j * DD + c]);
        *reinterpret_cast<__half*>(sm8 + WB_W1H + a) =
            __float2half_rn(W1b[(129 + j) * HH + c]);
    }
    if (tid < 128) {
        ((float*)(sm8 + WB_WOC))[tid]  = Wo[tid * DD + 128];
        ((float*)(sm8 + WB_W257))[tid] = W1b[257 * HH + tid];
        ((float*)(sm8 + WB_B1))[tid]   = b1b[tid];
    }
    for (int i = tid; i < DD; i += 256) ((float*)(sm8 + WB_BO))[i] = bo[i];
    __syncthreads();

    for (int r = wid; r < 128; r += 8) {
        const float* prow = g_pooled + (size_t)(rb + r) * HH;
        int c0 = lid * 4;
        float4 x = *reinterpret_cast<const float4*>(prow + c0);
        uint2 hv, lv;
        split2h(x.x, x.y, hv.x, lv.x);
        split2h(x.z, x.w, hv.y, lv.y);
        uint32_t a = SWZ(r, c0);
        *reinterpret_cast<uint2*>(sm8 + WB_AH + a) = hv;
        *reinterpret_cast<uint2*>(sm8 + WB_AL + a) = lv;
    }
    {
        const float* wocol = (const float*)(sm8 + WB_WOC);
        const float* bos   = (const float*)(sm8 + WB_BO);
        int r = tid >> 1, h = tid & 1;
        const float* prow = g_pooled + (size_t)(rb + r) * HH + h * 64;
        float s = 0.f;
#pragma unroll 4
        for (int j = 0; j < 64; j++) s = fmaf(prow[j], wocol[h * 64 + j], s);
        s += __shfl_xor_sync(0xffffffffu, s, 1);
        if (h == 0) {
            float v = s + __ldg(&src[(size_t)(rb + r) * DD + 128]) + bos[128];
            ((float*)(sm8 + WB_C1))[r] = v;
            g_interp[(size_t)(rb + r) * DD + 128] = v;
        }
    }
    __syncthreads();
    {
        float4 z = make_float4(0.f, 0.f, 0.f, 0.f);
        float4* gp = reinterpret_cast<float4*>(g_pooled + (size_t)rb * HH);
        for (int i = tid; i < 128 * HH / 4; i += 256) gp[i] = z;
    }

    float acc[2][8][4];
    ZERO_ACC2(acc)
    {
        const uint32_t pa[2] = {WB_AH, WB_AL};
#pragma unroll 1
        for (int p = 0; p < 2; p++)
            gemm128(smb, pa[p], WB_WOH, acc, warp_m, warp_n, lid);
    }
    __syncthreads();

    {
        const float* bos = (const float*)(sm8 + WB_BO);
        uint32_t* gsh = reinterpret_cast<uint32_t*>(g_srcH);
        uint32_t* gsl = reinterpret_cast<uint32_t*>(g_srcL);
#pragma unroll
        for (int mt = 0; mt < 2; mt++) {
            int row0 = warp_m * 32 + mt * 16 + (lid >> 2);
            int row1 = row0 + 8;
#pragma unroll
            for (int nt = 0; nt < 8; nt++) {
                int col = warp_n * 64 + nt * 8 + ((lid & 3) << 1);
                float2 BB = *reinterpret_cast<const float2*>(bos + col);
                size_t o0 = (size_t)(rb + row0) * DD + col;
                size_t o1 = (size_t)(rb + row1) * DD + col;
                float i00 = acc[mt][nt][0] + src[o0]     + BB.x;
                float i01 = acc[mt][nt][1] + src[o0 + 1] + BB.y;
                float i10 = acc[mt][nt][2] + src[o1]     + BB.x;
                float i11 = acc[mt][nt][3] + src[o1 + 1] + BB.y;
                g_interp[o0] = i00; g_interp[o0 + 1] = i01;
                g_interp[o1] = i10; g_interp[o1 + 1] = i11;
                uint32_t hi, lo;
                split2h(i00, i01, hi, lo);
                uint32_t a0 = SWZ(row0, col);
                *reinterpret_cast<uint32_t*>(sm8 + WB_AH + a0) = hi;
                *reinterpret_cast<uint32_t*>(sm8 + WB_AL + a0) = lo;
                gsh[((size_t)(rb + row0) * HH + col) >> 1] = hi;
                gsl[((size_t)(rb + row0) * HH + col) >> 1] = lo;
                split2h(i10, i11, hi, lo);
                uint32_t a1 = SWZ(row1, col);
                *reinterpret_cast<uint32_t*>(sm8 + WB_AH + a1) = hi;
                *reinterpret_cast<uint32_t*>(sm8 + WB_AL + a1) = lo;
                gsh[((size_t)(rb + row1) * HH + col) >> 1] = hi;
                gsl[((size_t)(rb + row1) * HH + col) >> 1] = lo;
            }
        }
    }
    __syncthreads();

    ZERO_ACC2(acc)
    {
        const uint32_t pa[2] = {WB_AH, WB_AL};
#pragma unroll 1
        for (int p = 0; p < 2; p++)
            gemm128(smb, pa[p], WB_W1H, acc, warp_m, warp_n, lid);
    }
    {
        const float* w7 = (const float*)(sm8 + WB_W257);
        const float* bb = (const float*)(sm8 + WB_B1);
        const float* c1 = (const float*)(sm8 + WB_C1);
#pragma unroll
        for (int mt = 0; mt < 2; mt++) {
            int row0 = warp_m * 32 + mt * 16 + (lid >> 2);
            int row1 = row0 + 8;
            float cv0 = c1[row0], cv1 = c1[row1];
#pragma unroll
            for (int nt = 0; nt < 8; nt++) {
                int col = warp_n * 64 + nt * 8 + ((lid & 3) << 1);
                float2 W7 = *reinterpret_cast<const float2*>(w7 + col);
                float2 BB = *reinterpret_cast<const float2*>(bb + col);
                float2 o0, o1;
                o0.x = acc[mt][nt][0] + BB.x + cv0 * W7.x;
                o0.y = acc[mt][nt][1] + BB.y + cv0 * W7.y;
                o1.x = acc[mt][nt][2] + BB.x + cv1 * W7.x;
                o1.y = acc[mt][nt][3] + BB.y + cv1 * W7.y;
                *reinterpret_cast<float2*>(g_base + (size_t)(rb + row0) * HH + col) = o0;
                *reinterpret_cast<float2*>(g_base + (size_t)(rb + row1) * HH + col) = o1;
            }
        }
    }
}

// ===========================================================================
// wofinal (256 thr): interp2 = g_interp + bo1 + pooled @ Wo1 (smem only),
// out = relu(interp2 @ fW1 + fb1) @ fW2 + fb2
// ===========================================================================
#define WF_WOH  0u
#define WF_AH   32768u
#define WF_AL   65536u
#define WF_FW   98304u
#define WF_FB1  131328u
#define WF_FW2  131584u
#define WF_BO   131840u
#define WF_C1   132384u
#define WF_WOC  132896u
#define SMEM_WF 133408u

__global__ void __launch_bounds__(256, 1)
wofinal_kernel(const float* __restrict__ Wo,
               const float* __restrict__ bo,
               const float* __restrict__ fW1, const float* __restrict__ fb1,
               const float* __restrict__ fW2, const float* __restrict__ fb2,
               float* __restrict__ out)
{
    extern __shared__ char sm8[];
    const uint32_t smb = smem_u32(sm8);
    const int tid = threadIdx.x;
    const int wid = tid >> 5, lid = tid & 31;
    const int warp_m = wid >> 1, warp_n = wid & 1;
    const int rb = blockIdx.x * 128;

    for (int idx = tid; idx < HH * HH; idx += 256) {
        int j = idx >> 7, c = idx & 127;
        *reinterpret_cast<__half*>(sm8 + WF_WOH + SWZ(c, j)) =
            __float2half_rn(Wo[j * DD + c]);
    }
    if (tid < 128) ((float*)(sm8 + WF_WOC))[tid] = Wo[tid * DD + 128];
    for (int i = tid; i < DD * 64; i += 256) ((float*)(sm8 + WF_FW))[i] = fW1[i];
    if (tid < 64) {
        ((float*)(sm8 + WF_FB1))[tid] = fb1[tid];
        ((float*)(sm8 + WF_FW2))[tid] = fW2[tid];
    }
    for (int i = tid; i < DD; i += 256) ((float*)(sm8 + WF_BO))[i] = bo[i];
    __syncthreads();

    for (int r = wid; r < 128; r += 8) {
        const float* prow = g_pooled + (size_t)(rb + r) * HH;
        int c0 = lid * 4;
        float4 x = *reinterpret_cast<const float4*>(prow + c0);
        uint2 hv, lv;
        split2h(x.x, x.y, hv.x, lv.x);
        split2h(x.z, x.w, hv.y, lv.y);
        uint32_t a = SWZ(r, c0);
        *reinterpret_cast<uint2*>(sm8 + WF_AH + a) = hv;
        *reinterpret_cast<uint2*>(sm8 + WF_AL + a) = lv;
    }
    {
        const float* wocol = (const float*)(sm8 + WF_WOC);
        const float* bos   = (const float*)(sm8 + WF_BO);
        int r = tid >> 1, h = tid & 1;
        const float* prow = g_pooled + (size_t)(rb + r) * HH + h * 64;
        float s = 0.f;
#pragma unroll 4
        for (int j = 0; j < 64; j++) s = fmaf(prow[j], wocol[h * 64 + j], s);
        s += __shfl_xor_sync(0xffffffffu, s, 1);
        if (h == 0)
            ((float*)(sm8 + WF_C1))[r] =
                s + __ldg(&g_interp[(size_t)(rb + r) * DD + 128]) + bos[128];
    }
    __syncthreads();

    float acc[2][8][4];
    ZERO_ACC2(acc)
    {
        const uint32_t pa[2] = {WF_AH, WF_AL};
#pragma unroll 1
        for (int p = 0; p < 2; p++)
            gemm128(smb, pa[p], WF_WOH, acc, warp_m, warp_n, lid);
    }
    __syncthreads();

    {
        const float* bos = (const float*)(sm8 + WF_BO);
        float* fT = (float*)(sm8 + WF_AH);
#pragma unroll
        for (int mt = 0; mt < 2; mt++) {
            int row0 = warp_m * 32 + mt * 16 + (lid >> 2);
            int row1 = row0 + 8;
#pragma unroll
            for (int nt = 0; nt < 8; nt++) {
                int col = warp_n * 64 + nt * 8 + ((lid & 3) << 1);
                float2 BB = *reinterpret_cast<const float2*>(bos + col);
                size_t o0 = (size_t)(rb + row0) * DD + col;
                size_t o1 = (size_t)(rb + row1) * DD + col;
                fT[col * 128 + row0]       = acc[mt][nt][0] + g_interp[o0]     + BB.x;
                fT[(col + 1) * 128 + row0] = acc[mt][nt][1] + g_interp[o0 + 1] + BB.y;
                fT[col * 128 + row1]       = acc[mt][nt][2] + g_interp[o1]     + BB.x;
                fT[(col + 1) * 128 + row1] = acc[mt][nt][3] + g_interp[o1 + 1] + BB.y;
            }
        }
    }
    __syncthreads();

    {
        const float* fT  = (const float*)(sm8 + WF_AH);
        const float* fw1 = (const float*)(sm8 + WF_FW);
        const float* fb1s = (const float*)(sm8 + WF_FB1);
        const float* fw2s = (const float*)(sm8 + WF_FW2);
        const float* c1  = (const float*)(sm8 + WF_C1);
        int r = tid >> 1, h = tid & 1;
        float hacc[32];
#pragma unroll
        for (int u = 0; u < 32; u++) hacc[u] = fb1s[h * 32 + u];
        for (int k = 0; k < 128; k++) {
            float xv = fT[k * 128 + r];
            const float4* wrow = reinterpret_cast<const float4*>(fw1 + k * 64 + h * 32);
#pragma unroll
            for (int u4 = 0; u4 < 8; u4++) {
                float4 w = wrow[u4];
                hacc[u4 * 4 + 0] = fmaf(xv, w.x, hacc[u4 * 4 + 0]);
                hacc[u4 * 4 + 1] = fmaf(xv, w.y, hacc[u4 * 4 + 1]);
                hacc[u4 * 4 + 2] = fmaf(xv, w.z, hacc[u4 * 4 + 2]);
                hacc[u4 * 4 + 3] = fmaf(xv, w.w, hacc[u4 * 4 + 3]);
            }
        }
        {
            float xv = c1[r];
            const float4* wrow = reinterpret_cast<const float4*>(fw1 + 128 * 64 + h * 32);
#pragma unroll
            for (int u4 = 0; u4 < 8; u4++) {
                float4 w = wrow[u4];
                hacc[u4 * 4 + 0] = fmaf(xv, w.x, hacc[u4 * 4 + 0]);
                hacc[u4 * 4 + 1] = fmaf(xv, w.y, hacc[u4 * 4 + 1]);
                hacc[u4 * 4 + 2] = fmaf(xv, w.z, hacc[u4 * 4 + 2]);
                hacc[u4 * 4 + 3] = fmaf(xv, w.w, hacc[u4 * 4 + 3]);
            }
        }
        float v = 0.f;
#pragma unroll
        for (int u = 0; u < 32; u++)
            v = fmaf(fmaxf(hacc[u], 0.f), fw2s[h * 32 + u], v);
        v += __shfl_xor_sync(0xffffffffu, v, 1);
        if (h == 0) out[rb + r] = v + __ldg(fb2);
    }
}

// ---------------------------------------------------------------------------
extern "C" void kernel_launch(void* const* d_in, const int* in_sizes, int n_in,
                              void* d_out, int out_size)
{
    (void)in_sizes; (void)n_in; (void)out_size;

    const float* interp_in = (const float*)d_in[0];
    const float* add_info  = (const float*)d_in[1];
    const int*   nbr       = (const int*)d_in[3];
    const int*   self      = (const int*)d_in[4];
    const float* b0W1 = (const float*)d_in[5];
    const float* b0b1 = (const float*)d_in[6];
    const float* b0W2 = (const float*)d_in[7];
    const float* b0b2 = (const float*)d_in[8];
    const float* b0Wo = (const float*)d_in[9];
    const float* b0bo = (const float*)d_in[10];
    const float* b1W1 = (const float*)d_in[11];
    const float* b1b1 = (const float*)d_in[12];
    const float* b1W2 = (const float*)d_in[13];
    const float* b1b2 = (const float*)d_in[14];
    const float* b1Wo = (const float*)d_in[15];
    const float* b1bo = (const float*)d_in[16];
    const float* fW1  = (const float*)d_in[17];
    const float* fb1  = (const float*)d_in[18];
    const float* fW2  = (const float*)d_in[19];
    const float* fb2  = (const float*)d_in[20];
    float* out = (float*)d_out;

    float* ginterp = nullptr;
    cudaGetSymbolAddress((void**)&ginterp, g_interp);

    int nsm = 148;
    cudaDeviceGetAttribute(&nsm, cudaDevAttrMultiProcessorCount, 0);

    cudaFuncSetAttribute(base0_kernel,
        cudaFuncAttributeMaxDynamicSharedMemorySize, (int)SMEM_B0);
    cudaFuncSetAttribute(edge_tc_kernel,
        cudaFuncAttributeMaxDynamicSharedMemorySize, (int)SMEM_EDGE);
    cudaFuncSetAttribute(wobase_kernel,
        cudaFuncAttributeMaxDynamicSharedMemorySize, (int)SMEM_WB);
    cudaFuncSetAttribute(wofinal_kernel,
        cudaFuncAttributeMaxDynamicSharedMemorySize, (int)SMEM_WF);

    base0_kernel<<<NODTILES, 256, SMEM_B0>>>(interp_in, b0W1, b0b1);
    edge_tc_kernel<<<nsm, 512, SMEM_EDGE>>>(interp_in, add_info, nbr, self,
                                            b0W1, b0W2, b0b2);
    wobase_kernel<<<NODTILES, 256, SMEM_WB>>>(interp_in, b0Wo, b0bo,
                                              b1W1, b1b1);
    edge_tc_kernel<<<nsm, 512, SMEM_EDGE>>>(ginterp, add_info, nbr, self,
                                            b1W1, b1W2, b1b2);
    wofinal_kernel<<<NODTILES, 256, SMEM_WF>>>(b1Wo, b1bo, fW1, fb1,
                                               fW2, fb2, out);
}

// round 17
// speedup vs baseline: 1.0928x; 1.0676x over previous
#include <cuda_runtime.h>
#include <cuda_fp16.h>
#include <cstdint>
#include <cstddef>

#define NN 15872
#define DD 129
#define HH 128
#define EE 253952
#define NMT 15872     // EE / 16 micro-tiles
#define NODTILES 124  // NN / 128 exactly

static __device__ float g_interp[NN * DD];
static __device__ float g_pooled[NN * HH];
static __device__ float g_base[NN * HH];
static __device__ __half g_srcH[NN * HH];
static __device__ __half g_srcL[NN * HH];

// ---------------------------------------------------------------------------
static __device__ __forceinline__ uint32_t smem_u32(const void* p) {
    uint32_t a;
    asm("{ .reg .u64 t; cvta.to.shared.u64 t, %1; cvt.u32.u64 %0, t; }"
        : "=r"(a) : "l"(p));
    return a;
}

// XOR-swizzled byte offset inside an fp16 tile (256B rows, 16B units)
#define SWZ(row, k) ((((uint32_t)(row)) << 8) + \
                     (((((uint32_t)(k) >> 3) ^ ((uint32_t)(row) & 7u))) << 4) + \
                     ((((uint32_t)(k)) & 7u) << 1))

#define LDMATRIX_X4(r0, r1, r2, r3, addr) \
    asm volatile("ldmatrix.sync.aligned.m8n8.x4.shared.b16 {%0,%1,%2,%3}, [%4];" \
                 : "=r"(r0), "=r"(r1), "=r"(r2), "=r"(r3) : "r"(addr))

#define MMA16816(d, a, b0, b1) \
    asm volatile("mma.sync.aligned.m16n8k16.row.col.f32.f16.f16.f32 " \
                 "{%0,%1,%2,%3}, {%4,%5,%6,%7}, {%8,%9}, {%0,%1,%2,%3};" \
                 : "+f"((d)[0]), "+f"((d)[1]), "+f"((d)[2]), "+f"((d)[3]) \
                 : "r"((a)[0]), "r"((a)[1]), "r"((a)[2]), "r"((a)[3]), \
                   "r"(b0), "r"(b1))

#define CP_ASYNC16(dst, src) \
    asm volatile("cp.async.cg.shared.global [%0], [%1], 16;" \
                 :: "r"(dst), "l"(src))
#define CP_COMMIT() asm volatile("cp.async.commit_group;")
#define CP_WAIT0()  asm volatile("cp.async.wait_group 0;" ::: "memory")

// fp16 hi/lo split of a pair of floats (hi: rounded, lo: residual)
static __device__ __forceinline__ void split2h(float a, float b,
                                               uint32_t& hi, uint32_t& lo) {
    __half2 h = __floats2half2_rn(a, b);
    float ar = a - __half2float(__low2half(h));
    float br = b - __half2float(__high2half(h));
    __half2 l = __floats2half2_rn(ar, br);
    hi = *reinterpret_cast<uint32_t*>(&h);
    lo = *reinterpret_cast<uint32_t*>(&l);
}

// ---------------------------------------------------------------------------
// One 128x128x128 fp16 GEMM pass, 8 warps, warp tile 32x64 (node kernels).
// ---------------------------------------------------------------------------
static __device__ __forceinline__ void gemm128(uint32_t smb, uint32_t offA,
                                               uint32_t offW,
                                               float (&acc)[2][8][4],
                                               int warp_m, int warp_n, int lid)
{
    const int mi  = lid >> 3;
    const int l7  = lid & 7;
    const int arow_d = l7 + ((mi & 1) << 3);
    const int akk_d  = (mi >> 1) << 3;
    const int brow_d = l7 + ((mi >> 1) << 3);
    const int bkk_d  = (mi & 1) << 3;

#pragma unroll
    for (int ks = 0; ks < 8; ks++) {
        const int k0 = ks * 16;
        uint32_t a[2][4];
#pragma unroll
        for (int mt = 0; mt < 2; mt++) {
            uint32_t ad = smb + offA +
                SWZ(warp_m * 32 + mt * 16 + arow_d, k0 + akk_d);
            LDMATRIX_X4(a[mt][0], a[mt][1], a[mt][2], a[mt][3], ad);
        }
#pragma unroll
        for (int q = 0; q < 4; q++) {
            uint32_t bd = smb + offW +
                SWZ(warp_n * 64 + q * 16 + brow_d, k0 + bkk_d);
            uint32_t b0, b1, b2, b3;
            LDMATRIX_X4(b0, b1, b2, b3, bd);
#pragma unroll
            for (int mt = 0; mt < 2; mt++) {
                MMA16816(acc[mt][2 * q + 0], a[mt], b0, b1);
                MMA16816(acc[mt][2 * q + 1], a[mt], b2, b3);
            }
        }
    }
}

// Fused 16x128x128 fp16 GEMM (2 combinations: Ah@Wh + Al@Wh), one warp pair;
// this warp handles columns warp_n*64..+64, rows 0..15 of the pair's tile.
static __device__ __forceinline__ void gemm_pair(
    uint32_t smb, uint32_t offAh, uint32_t offAl, uint32_t offWh,
    float (&acc)[8][4], int warp_n, int lid)
{
    const int mi  = lid >> 3;
    const int l7  = lid & 7;
    const int arow_d = l7 + ((mi & 1) << 3);
    const int akk_d  = (mi >> 1) << 3;
    const int brow_d = l7 + ((mi >> 1) << 3);
    const int bkk_d  = (mi & 1) << 3;

#pragma unroll
    for (int ks = 0; ks < 8; ks++) {
        const int k0 = ks * 16;
        uint32_t ah[4], al[4];
        {
            uint32_t sw = SWZ(arow_d, k0 + akk_d);
            LDMATRIX_X4(ah[0], ah[1], ah[2], ah[3], smb + offAh + sw);
            LDMATRIX_X4(al[0], al[1], al[2], al[3], smb + offAl + sw);
        }
#pragma unroll
        for (int q = 0; q < 4; q++) {
            uint32_t sw = SWZ(warp_n * 64 + q * 16 + brow_d, k0 + bkk_d);
            uint32_t b0, b1, b2, b3;
            LDMATRIX_X4(b0, b1, b2, b3, smb + offWh + sw);
            MMA16816(acc[2 * q + 0], ah, b0, b1);
            MMA16816(acc[2 * q + 1], ah, b2, b3);
            MMA16816(acc[2 * q + 0], al, b0, b1);
            MMA16816(acc[2 * q + 1], al, b2, b3);
        }
    }
}

#define ZERO_ACC2(acc) \
    { _Pragma("unroll") for (int i_ = 0; i_ < 2; i_++) \
      _Pragma("unroll") for (int j_ = 0; j_ < 8; j_++) \
      _Pragma("unroll") for (int c_ = 0; c_ < 4; c_++) acc[i_][j_][c_] = 0.f; }
#define ZERO_ACC1(acc) \
    { _Pragma("unroll") for (int j_ = 0; j_ < 8; j_++) \
      _Pragma("unroll") for (int c_ = 0; c_ < 4; c_++) acc[j_][c_] = 0.f; }

// ===========================================================================
// base0 (256 thr): g_base = b1 + src_main @ W1m ; preconvert src -> g_srcH/L,
// zero pooled.
// ===========================================================================
#define B0_WH   0u
#define B0_AH   32768u
#define B0_AL   65536u
#define B0_W257 98304u
#define B0_B1   98816u
#define B0_C1   99328u
#define SMEM_B0 99840u

__global__ void __launch_bounds__(256, 1)
base0_kernel(const float* __restrict__ src,
             const float* __restrict__ W1,
             const float* __restrict__ b1)
{
    extern __shared__ char sm8[];
    const uint32_t smb = smem_u32(sm8);
    const int tid = threadIdx.x;
    const int wid = tid >> 5, lid = tid & 31;
    const int warp_m = wid >> 1, warp_n = wid & 1;
    const int rb = blockIdx.x * 128;

    for (int idx = tid; idx < HH * HH; idx += 256) {
        int j = idx >> 7, t = idx & 127;
        float w = W1[(129 + j) * HH + t];
        *reinterpret_cast<__half*>(sm8 + B0_WH + SWZ(t, j)) = __float2half_rn(w);
    }
    if (tid < 128) {
        ((float*)(sm8 + B0_W257))[tid] = W1[257 * HH + tid];
        ((float*)(sm8 + B0_B1))[tid]   = b1[tid];
    }
    uint32_t* gsh = reinterpret_cast<uint32_t*>(g_srcH);
    uint32_t* gsl = reinterpret_cast<uint32_t*>(g_srcL);
    for (int r = wid; r < 128; r += 8) {
        const float* row = src + (size_t)(rb + r) * DD;
        int c0 = lid * 4;
        float x0 = __ldg(row + c0 + 0), x1 = __ldg(row + c0 + 1);
        float x2 = __ldg(row + c0 + 2), x3 = __ldg(row + c0 + 3);
        uint2 hv, lv;
        split2h(x0, x1, hv.x, lv.x);
        split2h(x2, x3, hv.y, lv.y);
        uint32_t a = SWZ(r, c0);
        *reinterpret_cast<uint2*>(sm8 + B0_AH + a) = hv;
        *reinterpret_cast<uint2*>(sm8 + B0_AL + a) = lv;
        size_t gi = ((size_t)(rb + r) * HH + c0) >> 1;
        *reinterpret_cast<uint2*>(&gsh[gi]) = hv;
        *reinterpret_cast<uint2*>(&gsl[gi]) = lv;
        if (lid == 0) ((float*)(sm8 + B0_C1))[r] = __ldg(row + 128);
    }
    {
        float4 z = make_float4(0.f, 0.f, 0.f, 0.f);
        float4* gp = reinterpret_cast<float4*>(g_pooled + (size_t)rb * HH);
        for (int i = tid; i < 128 * HH / 4; i += 256) gp[i] = z;
    }
    __syncthreads();

    float acc[2][8][4];
    ZERO_ACC2(acc)
    {
        const uint32_t pa[2] = {B0_AH, B0_AL};
#pragma unroll 1
        for (int p = 0; p < 2; p++)
            gemm128(smb, pa[p], B0_WH, acc, warp_m, warp_n, lid);
    }

    const float* w7 = (const float*)(sm8 + B0_W257);
    const float* bb = (const float*)(sm8 + B0_B1);
    const float* c1 = (const float*)(sm8 + B0_C1);
#pragma unroll
    for (int mt = 0; mt < 2; mt++) {
        int row0 = warp_m * 32 + mt * 16 + (lid >> 2);
        int row1 = row0 + 8;
        float cv0 = c1[row0], cv1 = c1[row1];
#pragma unroll
        for (int nt = 0; nt < 8; nt++) {
            int col = warp_n * 64 + nt * 8 + ((lid & 3) << 1);
            float2 W7 = *reinterpret_cast<const float2*>(w7 + col);
            float2 BB = *reinterpret_cast<const float2*>(bb + col);
            float2 o0, o1;
            o0.x = acc[mt][nt][0] + BB.x + cv0 * W7.x;
            o0.y = acc[mt][nt][1] + BB.y + cv0 * W7.y;
            o1.x = acc[mt][nt][2] + BB.x + cv1 * W7.x;
            o1.y = acc[mt][nt][3] + BB.y + cv1 * W7.y;
            *reinterpret_cast<float2*>(g_base + (size_t)(rb + row0) * HH + col) = o0;
            *reinterpret_cast<float2*>(g_base + (size_t)(rb + row1) * HH + col) = o1;
        }
    }
}

// ===========================================================================
// edge kernel: 512 threads = 8 INDEPENDENT 2-warp pipelines. Each pair owns a
// 16-edge micro-tile stream, its own A/H buffers (8KB each), its own 64-thread
// named barrier. Pairs share only the read-only weight tables.
// ===========================================================================
// pair p: A at p*8192 (AH, AL=+4096); H at 65536+p*8192 (HH, HL=+4096)
#define OFF_H     65536u
#define OFF_W1H   131072u
#define OFF_W2H   163840u
#define OFF_SELF  196608u   // 16 slots (8 pairs x 2 bufs) x 64B
#define OFF_C128  197632u
#define OFF_IOU   198656u
#define OFF_W128  199680u
#define OFF_W258  200192u
#define OFF_B2    200704u
#define SMEM_EDGE 201216u

__global__ void __launch_bounds__(512, 1)
edge_tc_kernel(const float* __restrict__ src,
               const float* __restrict__ add_info,
               const int*   __restrict__ nbr_idx,
               const int*   __restrict__ self_idx,
               const float* __restrict__ W1,
               const float* __restrict__ W2,
               const float* __restrict__ b2)
{
    extern __shared__ char sm8[];
    const uint32_t smb = smem_u32(sm8);
    const int tid = threadIdx.x;
    const int p   = tid >> 6;           // pair 0..7
    const int pt  = tid & 63;
    const int warp_n = pt >> 5;         // 0..1
    const int lid = pt & 31;

    const uint32_t offAH = (uint32_t)p * 8192u;
    const uint32_t offAL = offAH + 4096u;
    const uint32_t offHH = OFF_H + (uint32_t)p * 8192u;
    const uint32_t offHL = offHH + 4096u;

    const int grow = pt >> 2;           // 0..15
    const int half = (pt >> 1) & 1;
    const int part = pt & 1;
    const __half* gsrc = half ? g_srcL : g_srcH;
    const uint32_t dstbase = smb + (half ? offAL : offAH) +
                             ((uint32_t)grow << 8);
    const uint32_t grx = (uint32_t)(grow & 7);

    int*   selfp[2] = {(int*)(sm8 + OFF_SELF + (p * 2 + 0) * 64),
                       (int*)(sm8 + OFF_SELF + (p * 2 + 1) * 64)};
    float* c128p[2] = {(float*)(sm8 + OFF_C128 + (p * 2 + 0) * 64),
                       (float*)(sm8 + OFF_C128 + (p * 2 + 1) * 64)};
    float* ioup[2]  = {(float*)(sm8 + OFF_IOU + (p * 2 + 0) * 64),
                       (float*)(sm8 + OFF_IOU + (p * 2 + 1) * 64)};

    const int stride8 = gridDim.x * 8;
    int mt = blockIdx.x * 8 + p;

    // ---- prologue: prefetch first micro-tile into buf 0 ----
    {
        int nb = __ldg(&nbr_idx[mt * 16 + grow]);
        if ((pt & 3) == 0) {
            selfp[0][grow] = __ldg(&self_idx[mt * 16 + grow]);
            c128p[0][grow] = __ldg(&src[(size_t)nb * DD + 128]);
            ioup[0][grow]  = __ldg(&add_info[mt * 16 + grow]);
        }
        const __half* rowp = gsrc + ((size_t)nb << 7);
#pragma unroll
        for (int uu = 0; uu < 8; uu++) {
            uint32_t u = (uint32_t)(part * 8 + uu);
            CP_ASYNC16(dstbase + ((u ^ grx) << 4), rowp + u * 8);
        }
        CP_COMMIT();
    }

    // ---- stage weights (all 512 threads; overlaps in-flight gathers) ----
    for (int idx = tid; idx < HH * HH; idx += 512) {
        int h = idx & 127, k = idx >> 7;
        uint32_t a = SWZ(h, k);
        *reinterpret_cast<__half*>(sm8 + OFF_W1H + a) = __float2half_rn(W1[idx]);
        *reinterpret_cast<__half*>(sm8 + OFF_W2H + a) = __float2half_rn(W2[idx]);
    }
    if (tid < 128) {
        ((float*)(sm8 + OFF_W128))[tid] = W1[128 * HH + tid];
        ((float*)(sm8 + OFF_W258))[tid] = W1[258 * HH + tid];
        ((float*)(sm8 + OFF_B2))[tid]   = b2[tid];
    }
    CP_WAIT0();
    __syncthreads();

    const float* w128s = (const float*)(sm8 + OFF_W128);
    const float* w258s = (const float*)(sm8 + OFF_W258);
    const float* b2s   = (const float*)(sm8 + OFF_B2);

#define BARP() asm volatile("bar.sync %0, 64;" :: "r"(p + 1) : "memory")

    int buf = 0;
    for (; mt < NMT; mt += stride8) {
        const int nmt = mt + stride8;

        const int*   selfs = selfp[buf];
        const float* c128s = c128p[buf];
        const float* ious  = ioup[buf];

        // ---- layer-1 fused GEMM (reads pair's A) ----
        float acc[8][4];
        ZERO_ACC1(acc)
        gemm_pair(smb, offAH, offAL, OFF_W1H, acc, warp_n, lid);
        BARP();   // both warps' A reads done -> A free

        // ---- prefetch next micro-tile into A (covers epi1+GEMM2+epi2) ----
        if (nmt < NMT) {
            int nb_next = __ldg(&nbr_idx[nmt * 16 + grow]);
            if ((pt & 3) == 0) {
                selfp[buf ^ 1][grow] = __ldg(&self_idx[nmt * 16 + grow]);
                c128p[buf ^ 1][grow] = __ldg(&src[(size_t)nb_next * DD + 128]);
                ioup[buf ^ 1][grow]  = __ldg(&add_info[nmt * 16 + grow]);
            }
            const __half* rowp = gsrc + ((size_t)nb_next << 7);
#pragma unroll
            for (int uu = 0; uu < 8; uu++) {
                uint32_t u = (uint32_t)(part * 8 + uu);
                CP_ASYNC16(dstbase + ((u ^ grx) << 4), rowp + u * 8);
            }
            CP_COMMIT();
        }

        // ---- epilogue 1: finish layer-1, relu, write pair's H buffer ----
        {
            int row0 = lid >> 2;
            int row1 = row0 + 8;
            int s0 = selfs[row0], s1 = selfs[row1];
            float cA0 = c128s[row0], cA1 = c128s[row1];
            float iv0 = ious[row0],  iv1 = ious[row1];
            const float* bp0 = g_base + (size_t)s0 * HH;
            const float* bp1 = g_base + (size_t)s1 * HH;
#pragma unroll
            for (int nt = 0; nt < 8; nt++) {
                int col = warp_n * 64 + nt * 8 + ((lid & 3) << 1);
                float2 B0 = *reinterpret_cast<const float2*>(bp0 + col);
                float2 B1 = *reinterpret_cast<const float2*>(bp1 + col);
                float2 WA = *reinterpret_cast<const float2*>(w128s + col);
                float2 WI = *reinterpret_cast<const float2*>(w258s + col);
                float h00 = fmaxf(acc[nt][0] + B0.x + cA0 * WA.x + iv0 * WI.x, 0.f);
                float h01 = fmaxf(acc[nt][1] + B0.y + cA0 * WA.y + iv0 * WI.y, 0.f);
                float h10 = fmaxf(acc[nt][2] + B1.x + cA1 * WA.x + iv1 * WI.x, 0.f);
                float h11 = fmaxf(acc[nt][3] + B1.y + cA1 * WA.y + iv1 * WI.y, 0.f);
                uint32_t hi, lo;
                split2h(h00, h01, hi, lo);
                uint32_t a0 = SWZ(row0, col);
                *reinterpret_cast<uint32_t*>(sm8 + offHH + a0) = hi;
                *reinterpret_cast<uint32_t*>(sm8 + offHL + a0) = lo;
                split2h(h10, h11, hi, lo);
                uint32_t a1 = SWZ(row1, col);
                *reinterpret_cast<uint32_t*>(sm8 + offHH + a1) = hi;
                *reinterpret_cast<uint32_t*>(sm8 + offHL + a1) = lo;
            }
        }
        BARP();   // H ready (both warps)

        // ---- layer-2 fused GEMM (reads pair's H) ----
        ZERO_ACC1(acc)
        gemm_pair(smb, offHH, offHL, OFF_W2H, acc, warp_n, lid);

        // ---- epilogue 2: bias + relu + merged segment atomicMax ----
        {
            int row0 = lid >> 2;
            int s0 = selfs[row0], s1 = selfs[row0 + 8];
            int* gp = reinterpret_cast<int*>(g_pooled);
#pragma unroll
            for (int nt = 0; nt < 8; nt++) {
                int col = warp_n * 64 + nt * 8 + ((lid & 3) << 1);
#pragma unroll
                for (int c = 0; c < 2; c++) {
                    float bv = b2s[col + c];
                    float v0 = fmaxf(acc[nt][0 + c] + bv, 0.f);
                    float v1 = fmaxf(acc[nt][2 + c] + bv, 0.f);
                    if (s0 == s1) {
                        atomicMax(gp + (size_t)s0 * HH + col + c,
                                  __float_as_int(fmaxf(v0, v1)));
                    } else {
                        atomicMax(gp + (size_t)s0 * HH + col + c,
                                  __float_as_int(v0));
                        atomicMax(gp + (size_t)s1 * HH + col + c,
                                  __float_as_int(v1));
                    }
                }
            }
        }

        CP_WAIT0();   // next-tile A transfer (issued before epi1)
        BARP();       // A + scalars visible; orders H reads vs next epi1
        buf ^= 1;
    }
#undef BARP
}

// ===========================================================================
// wobase (256 thr): interp1 = src + bo0 + pooled @ Wo0 (write g_interp,
// g_srcH/L), then g_base = b1_1 + interp1_main @ W1m_1 ; zero g_pooled.
// ===========================================================================
#define WB_WOH  0u
#define WB_W1H  32768u
#define WB_AH   65536u
#define WB_AL   98304u
#define WB_BO   131072u
#define WB_B1   131616u
#define WB_W257 132128u
#define WB_WOC  132640u
#define WB_C1   133152u
#define SMEM_WB 133664u

__global__ void __launch_bounds__(256, 1)
wobase_kernel(const float* __restrict__ src,
              const float* __restrict__ Wo,
              const float* __restrict__ bo,
              const float* __restrict__ W1b,
              const float* __restrict__ b1b)
{
    extern __shared__ char sm8[];
    const uint32_t smb = smem_u32(sm8);
    const int tid = threadIdx.x;
    const int wid = tid >> 5, lid = tid & 31;
    const int warp_m = wid >> 1, warp_n = wid & 1;
    const int rb = blockIdx.x * 128;

    for (int idx = tid; idx < HH * HH; idx += 256) {
        int j = idx >> 7, c = idx & 127;
        uint32_t a = SWZ(c, j);
        *reinterpret_cast<__half*>(sm8 + WB_WOH + a) =
            __float2half_rn(Wo[j * DD + c]);
        *reinterpret_cast<__half*>(sm8 + WB_W1H + a) =
            __float2half_rn(W1b[(129 + j) * HH + c]);
    }
    if (tid < 128) {
        ((float*)(sm8 + WB_WOC))[tid]  = Wo[tid * DD + 128];
        ((float*)(sm8 + WB_W257))[tid] = W1b[257 * HH + tid];
        ((float*)(sm8 + WB_B1))[tid]   = b1b[tid];
    }
    for (int i = tid; i < DD; i += 256) ((float*)(sm8 + WB_BO))[i] = bo[i];
    __syncthreads();

    for (int r = wid; r < 128; r += 8) {
        const float* prow = g_pooled + (size_t)(rb + r) * HH;
        int c0 = lid * 4;
        float4 x = *reinterpret_cast<const float4*>(prow + c0);
        uint2 hv, lv;
        split2h(x.x, x.y, hv.x, lv.x);
        split2h(x.z, x.w, hv.y, lv.y);
        uint32_t a = SWZ(r, c0);
        *reinterpret_cast<uint2*>(sm8 + WB_AH + a) = hv;
        *reinterpret_cast<uint2*>(sm8 + WB_AL + a) = lv;
    }
    {
        const float* wocol = (const float*)(sm8 + WB_WOC);
        const float* bos   = (const float*)(sm8 + WB_BO);
        int r = tid >> 1, h = tid & 1;
        const float* prow = g_pooled + (size_t)(rb + r) * HH + h * 64;
        float s = 0.f;
#pragma unroll 4
        for (int j = 0; j < 64; j++) s = fmaf(prow[j], wocol[h * 64 + j], s);
        s += __shfl_xor_sync(0xffffffffu, s, 1);
        if (h == 0) {
            float v = s + __ldg(&src[(size_t)(rb + r) * DD + 128]) + bos[128];
            ((float*)(sm8 + WB_C1))[r] = v;
            g_interp[(size_t)(rb + r) * DD + 128] = v;
        }
    }
    __syncthreads();
    {
        float4 z = make_float4(0.f, 0.f, 0.f, 0.f);
        float4* gp = reinterpret_cast<float4*>(g_pooled + (size_t)rb * HH);
        for (int i = tid; i < 128 * HH / 4; i += 256) gp[i] = z;
    }

    float acc[2][8][4];
    ZERO_ACC2(acc)
    {
        const uint32_t pa[2] = {WB_AH, WB_AL};
#pragma unroll 1
        for (int p = 0; p < 2; p++)
            gemm128(smb, pa[p], WB_WOH, acc, warp_m, warp_n, lid);
    }
    __syncthreads();

    {
        const float* bos = (const float*)(sm8 + WB_BO);
        uint32_t* gsh = reinterpret_cast<uint32_t*>(g_srcH);
        uint32_t* gsl = reinterpret_cast<uint32_t*>(g_srcL);
#pragma unroll
        for (int mt = 0; mt < 2; mt++) {
            int row0 = warp_m * 32 + mt * 16 + (lid >> 2);
            int row1 = row0 + 8;
#pragma unroll
            for (int nt = 0; nt < 8; nt++) {
                int col = warp_n * 64 + nt * 8 + ((lid & 3) << 1);
                float2 BB = *reinterpret_cast<const float2*>(bos + col);
                size_t o0 = (size_t)(rb + row0) * DD + col;
                size_t o1 = (size_t)(rb + row1) * DD + col;
                float i00 = acc[mt][nt][0] + src[o0]     + BB.x;
                float i01 = acc[mt][nt][1] + src[o0 + 1] + BB.y;
                float i10 = acc[mt][nt][2] + src[o1]     + BB.x;
                float i11 = acc[mt][nt][3] + src[o1 + 1] + BB.y;
                g_interp[o0] = i00; g_interp[o0 + 1] = i01;
                g_interp[o1] = i10; g_interp[o1 + 1] = i11;
                uint32_t hi, lo;
                split2h(i00, i01, hi, lo);
                uint32_t a0 = SWZ(row0, col);
                *reinterpret_cast<uint32_t*>(sm8 + WB_AH + a0) = hi;
                *reinterpret_cast<uint32_t*>(sm8 + WB_AL + a0) = lo;
                gsh[((size_t)(rb + row0) * HH + col) >> 1] = hi;
                gsl[((size_t)(rb + row0) * HH + col) >> 1] = lo;
                split2h(i10, i11, hi, lo);
                uint32_t a1 = SWZ(row1, col);
                *reinterpret_cast<uint32_t*>(sm8 + WB_AH + a1) = hi;
                *reinterpret_cast<uint32_t*>(sm8 + WB_AL + a1) = lo;
                gsh[((size_t)(rb + row1) * HH + col) >> 1] = hi;
                gsl[((size_t)(rb + row1) * HH + col) >> 1] = lo;
            }
        }
    }
    __syncthreads();

    ZERO_ACC2(acc)
    {
        const uint32_t pa[2] = {WB_AH, WB_AL};
#pragma unroll 1
        for (int p = 0; p < 2; p++)
            gemm128(smb, pa[p], WB_W1H, acc, warp_m, warp_n, lid);
    }
    {
        const float* w7 = (const float*)(sm8 + WB_W257);
        const float* bb = (const float*)(sm8 + WB_B1);
        const float* c1 = (const float*)(sm8 + WB_C1);
#pragma unroll
        for (int mt = 0; mt < 2; mt++) {
            int row0 = warp_m * 32 + mt * 16 + (lid >> 2);
            int row1 = row0 + 8;
            float cv0 = c1[row0], cv1 = c1[row1];
#pragma unroll
            for (int nt = 0; nt < 8; nt++) {
                int col = warp_n * 64 + nt * 8 + ((lid & 3) << 1);
                float2 W7 = *reinterpret_cast<const float2*>(w7 + col);
                float2 BB = *reinterpret_cast<const float2*>(bb + col);
                float2 o0, o1;
                o0.x = acc[mt][nt][0] + BB.x + cv0 * W7.x;
                o0.y = acc[mt][nt][1] + BB.y + cv0 * W7.y;
                o1.x = acc[mt][nt][2] + BB.x + cv1 * W7.x;
                o1.y = acc[mt][nt][3] + BB.y + cv1 * W7.y;
                *reinterpret_cast<float2*>(g_base + (size_t)(rb + row0) * HH + col) = o0;
                *reinterpret_cast<float2*>(g_base + (size_t)(rb + row1) * HH + col) = o1;
            }
        }
    }
}

// ===========================================================================
// wofinal (256 thr): interp2 = g_interp + bo1 + pooled @ Wo1 (smem only),
// out = relu(interp2 @ fW1 + fb1) @ fW2 + fb2
// ===========================================================================
#define WF_WOH  0u
#define WF_AH   32768u
#define WF_AL   65536u
#define WF_FW   98304u
#define WF_FB1  131328u
#define WF_FW2  131584u
#define WF_BO   131840u
#define WF_C1   132384u
#define WF_WOC  132896u
#define SMEM_WF 133408u

__global__ void __launch_bounds__(256, 1)
wofinal_kernel(const float* __restrict__ Wo,
               const float* __restrict__ bo,
               const float* __restrict__ fW1, const float* __restrict__ fb1,
               const float* __restrict__ fW2, const float* __restrict__ fb2,
               float* __restrict__ out)
{
    extern __shared__ char sm8[];
    const uint32_t smb = smem_u32(sm8);
    const int tid = threadIdx.x;
    const int wid = tid >> 5, lid = tid & 31;
    const int warp_m = wid >> 1, warp_n = wid & 1;
    const int rb = blockIdx.x * 128;

    for (int idx = tid; idx < HH * HH; idx += 256) {
        int j = idx >> 7, c = idx & 127;
        *reinterpret_cast<__half*>(sm8 + WF_WOH + SWZ(c, j)) =
            __float2half_rn(Wo[j * DD + c]);
    }
    if (tid < 128) ((float*)(sm8 + WF_WOC))[tid] = Wo[tid * DD + 128];
    for (int i = tid; i < DD * 64; i += 256) ((float*)(sm8 + WF_FW))[i] = fW1[i];
    if (tid < 64) {
        ((float*)(sm8 + WF_FB1))[tid] = fb1[tid];
        ((float*)(sm8 + WF_FW2))[tid] = fW2[tid];
    }
    for (int i = tid; i < DD; i += 256) ((float*)(sm8 + WF_BO))[i] = bo[i];
    __syncthreads();

    for (int r = wid; r < 128; r += 8) {
        const float* prow = g_pooled + (size_t)(rb + r) * HH;
        int c0 = lid * 4;
        float4 x = *reinterpret_cast<const float4*>(prow + c0);
        uint2 hv, lv;
        split2h(x.x, x.y, hv.x, lv.x);
        split2h(x.z, x.w, hv.y, lv.y);
        uint32_t a = SWZ(r, c0);
        *reinterpret_cast<uint2*>(sm8 + WF_AH + a) = hv;
        *reinterpret_cast<uint2*>(sm8 + WF_AL + a) = lv;
    }
    {
        const float* wocol = (const float*)(sm8 + WF_WOC);
        const float* bos   = (const float*)(sm8 + WF_BO);
        int r = tid >> 1, h = tid & 1;
        const float* prow = g_pooled + (size_t)(rb + r) * HH + h * 64;
        float s = 0.f;
#pragma unroll 4
        for (int j = 0; j < 64; j++) s = fmaf(prow[j], wocol[h * 64 + j], s);
        s += __shfl_xor_sync(0xffffffffu, s, 1);
        if (h == 0)
            ((float*)(sm8 + WF_C1))[r] =
                s + __ldg(&g_interp[(size_t)(rb + r) * DD + 128]) + bos[128];
    }
    __syncthreads();

    float acc[2][8][4];
    ZERO_ACC2(acc)
    {
        const uint32_t pa[2] = {WF_AH, WF_AL};
#pragma unroll 1
        for (int p = 0; p < 2; p++)
            gemm128(smb, pa[p], WF_WOH, acc, warp_m, warp_n, lid);
    }
    __syncthreads();

    {
        const float* bos = (const float*)(sm8 + WF_BO);
        float* fT = (float*)(sm8 + WF_AH);
#pragma unroll
        for (int mt = 0; mt < 2; mt++) {
            int row0 = warp_m * 32 + mt * 16 + (lid >> 2);
            int row1 = row0 + 8;
#pragma unroll
            for (int nt = 0; nt < 8; nt++) {
                int col = warp_n * 64 + nt * 8 + ((lid & 3) << 1);
                float2 BB = *reinterpret_cast<const float2*>(bos + col);
                size_t o0 = (size_t)(rb + row0) * DD + col;
                size_t o1 = (size_t)(rb + row1) * DD + col;
                fT[col * 128 + row0]       = acc[mt][nt][0] + g_interp[o0]     + BB.x;
                fT[(col + 1) * 128 + row0] = acc[mt][nt][1] + g_interp[o0 + 1] + BB.y;
                fT[col * 128 + row1]       = acc[mt][nt][2] + g_interp[o1]     + BB.x;
                fT[(col + 1) * 128 + row1] = acc[mt][nt][3] + g_interp[o1 + 1] + BB.y;
            }
        }
    }
    __syncthreads();

    {
        const float* fT  = (const float*)(sm8 + WF_AH);
        const float* fw1 = (const float*)(sm8 + WF_FW);
        const float* fb1s = (const float*)(sm8 + WF_FB1);
        const float* fw2s = (const float*)(sm8 + WF_FW2);
        const float* c1  = (const float*)(sm8 + WF_C1);
        int r = tid >> 1, h = tid & 1;
        float hacc[32];
#pragma unroll
        for (int u = 0; u < 32; u++) hacc[u] = fb1s[h * 32 + u];
        for (int k = 0; k < 128; k++) {
            float xv = fT[k * 128 + r];
            const float4* wrow = reinterpret_cast<const float4*>(fw1 + k * 64 + h * 32);
#pragma unroll
            for (int u4 = 0; u4 < 8; u4++) {
                float4 w = wrow[u4];
                hacc[u4 * 4 + 0] = fmaf(xv, w.x, hacc[u4 * 4 + 0]);
                hacc[u4 * 4 + 1] = fmaf(xv, w.y, hacc[u4 * 4 + 1]);
                hacc[u4 * 4 + 2] = fmaf(xv, w.z, hacc[u4 * 4 + 2]);
                hacc[u4 * 4 + 3] = fmaf(xv, w.w, hacc[u4 * 4 + 3]);
            }
        }
        {
            float xv = c1[r];
            const float4* wrow = reinterpret_cast<const float4*>(fw1 + 128 * 64 + h * 32);
#pragma unroll
            for (int u4 = 0; u4 < 8; u4++) {
                float4 w = wrow[u4];
                hacc[u4 * 4 + 0] = fmaf(xv, w.x, hacc[u4 * 4 + 0]);
                hacc[u4 * 4 + 1] = fmaf(xv, w.y, hacc[u4 * 4 + 1]);
                hacc[u4 * 4 + 2] = fmaf(xv, w.z, hacc[u4 * 4 + 2]);
                hacc[u4 * 4 + 3] = fmaf(xv, w.w, hacc[u4 * 4 + 3]);
            }
        }
        float v = 0.f;
#pragma unroll
        for (int u = 0; u < 32; u++)
            v = fmaf(fmaxf(hacc[u], 0.f), fw2s[h * 32 + u], v);
        v += __shfl_xor_sync(0xffffffffu, v, 1);
        if (h == 0) out[rb + r] = v + __ldg(fb2);
    }
}

// ---------------------------------------------------------------------------
extern "C" void kernel_launch(void* const* d_in, const int* in_sizes, int n_in,
                              void* d_out, int out_size)
{
    (void)in_sizes; (void)n_in; (void)out_size;

    const float* interp_in = (const float*)d_in[0];
    const float* add_info  = (const float*)d_in[1];
    const int*   nbr       = (const int*)d_in[3];
    const int*   self      = (const int*)d_in[4];
    const float* b0W1 = (const float*)d_in[5];
    const float* b0b1 = (const float*)d_in[6];
    const float* b0W2 = (const float*)d_in[7];
    const float* b0b2 = (const float*)d_in[8];
    const float* b0Wo = (const float*)d_in[9];
    const float* b0bo = (const float*)d_in[10];
    const float* b1W1 = (const float*)d_in[11];
    const float* b1b1 = (const float*)d_in[12];
    const float* b1W2 = (const float*)d_in[13];
    const float* b1b2 = (const float*)d_in[14];
    const float* b1Wo = (const float*)d_in[15];
    const float* b1bo = (const float*)d_in[16];
    const float* fW1  = (const float*)d_in[17];
    const float* fb1  = (const float*)d_in[18];
    const float* fW2  = (const float*)d_in[19];
    const float* fb2  = (const float*)d_in[20];
    float* out = (float*)d_out;

    float* ginterp = nullptr;
    cudaGetSymbolAddress((void**)&ginterp, g_interp);

    int nsm = 148;
    cudaDeviceGetAttribute(&nsm, cudaDevAttrMultiProcessorCount, 0);

    cudaFuncSetAttribute(base0_kernel,
        cudaFuncAttributeMaxDynamicSharedMemorySize, (int)SMEM_B0);
    cudaFuncSetAttribute(edge_tc_kernel,
        cudaFuncAttributeMaxDynamicSharedMemorySize, (int)SMEM_EDGE);
    cudaFuncSetAttribute(wobase_kernel,
        cudaFuncAttributeMaxDynamicSharedMemorySize, (int)SMEM_WB);
    cudaFuncSetAttribute(wofinal_kernel,
        cudaFuncAttributeMaxDynamicSharedMemorySize, (int)SMEM_WF);

    base0_kernel<<<NODTILES, 256, SMEM_B0>>>(interp_in, b0W1, b0b1);
    edge_tc_kernel<<<nsm, 512, SMEM_EDGE>>>(interp_in, add_info, nbr, self,
                                            b0W1, b0W2, b0b2);
    wobase_kernel<<<NODTILES, 256, SMEM_WB>>>(interp_in, b0Wo, b0bo,
                                              b1W1, b1b1);
    edge_tc_kernel<<<nsm, 512, SMEM_EDGE>>>(ginterp, add_info, nbr, self,
                                            b1W1, b1W2, b1b2);
    wofinal_kernel<<<NODTILES, 256, SMEM_WF>>>(b1Wo, b1bo, fW1, fb1,
                                               fW2, fb2, out);
}